// round 1
// baseline (speedup 1.0000x reference)
#include <cuda_runtime.h>
#include <math.h>

#define DIM   2048
#define NH    16
#define HD    128
#define SEQ   2048
#define BATCH 2
#define MROWS (BATCH*SEQ)   // 4096

// ---- scratch (device globals; no allocations allowed) ----
__device__ float g_Q[(size_t)MROWS*DIM];
__device__ float g_K[(size_t)MROWS*DIM];
__device__ float g_V[(size_t)MROWS*DIM];
__device__ float g_A[(size_t)MROWS*DIM];

// ============================================================
// SGEMM: C[M,N] = A[M,K] @ B[K,N], all row-major, fp32.
// 128x128 block tile, BK=8, 8x8 per-thread microtile, 256 threads.
// ============================================================
#define BM 128
#define BN 128
#define BKg 8
#define TM 8
#define TN 8

__global__ __launch_bounds__(256) void sgemm_kernel(
    const float* __restrict__ A, const float* __restrict__ B,
    float* __restrict__ C, int M, int N, int K)
{
    __shared__ float As[BKg][BM];
    __shared__ float Bs[BKg][BN];

    const int tid  = threadIdx.x;
    const int row0 = blockIdx.y * BM;
    const int col0 = blockIdx.x * BN;
    const int tr = tid / 16;     // 0..15
    const int tc = tid % 16;     // 0..15

    float acc[TM][TN];
#pragma unroll
    for (int i = 0; i < TM; i++)
#pragma unroll
        for (int j = 0; j < TN; j++) acc[i][j] = 0.f;

    const int aRow = tid >> 1;          // 0..127
    const int aCol = (tid & 1) * 4;     // 0 or 4
    const int bRow = tid >> 5;          // 0..7
    const int bCol = (tid & 31) * 4;    // 0..124

    const float* Aptr = A + (size_t)row0 * K;
    const float* Bptr = B + col0;

    for (int k0 = 0; k0 < K; k0 += BKg) {
        float4 a4 = *(const float4*)(Aptr + (size_t)aRow * K + k0 + aCol);
        As[aCol + 0][aRow] = a4.x;
        As[aCol + 1][aRow] = a4.y;
        As[aCol + 2][aRow] = a4.z;
        As[aCol + 3][aRow] = a4.w;
        float4 b4 = *(const float4*)(Bptr + (size_t)(k0 + bRow) * N + bCol);
        *(float4*)&Bs[bRow][bCol] = b4;
        __syncthreads();

#pragma unroll
        for (int k = 0; k < BKg; k++) {
            float4 ra0 = *(const float4*)&As[k][tr * TM];
            float4 ra1 = *(const float4*)&As[k][tr * TM + 4];
            float4 rb0 = *(const float4*)&Bs[k][tc * TN];
            float4 rb1 = *(const float4*)&Bs[k][tc * TN + 4];
            float ra[TM] = {ra0.x, ra0.y, ra0.z, ra0.w, ra1.x, ra1.y, ra1.z, ra1.w};
            float rb[TN] = {rb0.x, rb0.y, rb0.z, rb0.w, rb1.x, rb1.y, rb1.z, rb1.w};
#pragma unroll
            for (int i = 0; i < TM; i++)
#pragma unroll
                for (int j = 0; j < TN; j++)
                    acc[i][j] += ra[i] * rb[j];
        }
        __syncthreads();
    }

#pragma unroll
    for (int i = 0; i < TM; i++) {
        float* Crow = C + (size_t)(row0 + tr * TM + i) * N + col0 + tc * TN;
        *(float4*)(Crow)     = make_float4(acc[i][0], acc[i][1], acc[i][2], acc[i][3]);
        *(float4*)(Crow + 4) = make_float4(acc[i][4], acc[i][5], acc[i][6], acc[i][7]);
    }
}

// ============================================================
// RoPE on Q and K (in place). Q additionally pre-scaled by 1/sqrt(HD).
// ============================================================
__global__ __launch_bounds__(256) void rope_kernel(
    float* __restrict__ Q, float* __restrict__ K,
    const float* __restrict__ fcos, const float* __restrict__ fsin)
{
    const int half = HD / 2;
    int idx = blockIdx.x * blockDim.x + threadIdx.x;   // over MROWS*NH*half
    if (idx >= MROWS * NH * half) return;
    int i   = idx % half;
    int tmp = idx / half;
    int h   = tmp % NH;
    int rs  = tmp / NH;           // b*SEQ + s
    int s   = rs % SEQ;

    float c  = fcos[s * half + i];
    float sn = fsin[s * half + i];
    size_t base = (size_t)rs * DIM + h * HD + 2 * i;

    const float qscale = 0.08838834764831845f;  // 1/sqrt(128)
    float q0 = Q[base], q1 = Q[base + 1];
    Q[base]     = (q0 * c - q1 * sn) * qscale;
    Q[base + 1] = (q0 * sn + q1 * c) * qscale;
    float k0 = K[base], k1 = K[base + 1];
    K[base]     = k0 * c - k1 * sn;
    K[base + 1] = k0 * sn + k1 * c;
}

// ============================================================
// Causal flash attention, fp32. 64x64 tiles, Hd=128, 256 threads.
// ============================================================
#define BQ  64
#define BKV 64
#define QPAD (HD + 1)
#define SPAD (BKV + 1)
#define ATTN_SMEM_FLOATS (2 * BQ * QPAD + BQ * SPAD + 2 * BQ)
#define ATTN_SMEM_BYTES  (ATTN_SMEM_FLOATS * 4)

__global__ __launch_bounds__(256) void attn_kernel(
    const float* __restrict__ Q, const float* __restrict__ K,
    const float* __restrict__ V, float* __restrict__ O)
{
    extern __shared__ float sm[];
    float (*Qs)[QPAD]  = (float(*)[QPAD])sm;
    float (*KVs)[QPAD] = (float(*)[QPAD])(sm + BQ * QPAD);
    float (*Ss)[SPAD]  = (float(*)[SPAD])(sm + 2 * BQ * QPAD);
    float* rowScale    = sm + 2 * BQ * QPAD + BQ * SPAD;
    float* rowSum      = rowScale + BQ;

    const int tid = threadIdx.x;
    const int qb = blockIdx.x, h = blockIdx.y, b = blockIdx.z;
    const int q0 = qb * BQ;

    const float* Qbase = Q + (size_t)b * SEQ * DIM + h * HD;
    const float* Kbase = K + (size_t)b * SEQ * DIM + h * HD;
    const float* Vbase = V + (size_t)b * SEQ * DIM + h * HD;

    // load Q tile
    for (int e = tid; e < BQ * HD; e += 256) {
        int r = e >> 7, d = e & 127;
        Qs[r][d] = Qbase[(size_t)(q0 + r) * DIM + d];
    }

    // PV accumulator layout: thread owns 2 rows x 16 d
    const int pr = tid >> 3;           // row pair 0..31
    const int dg = (tid & 7) * 16;     // d group
    float o0[16], o1[16];
#pragma unroll
    for (int d = 0; d < 16; d++) { o0[d] = 0.f; o1[d] = 0.f; }

    // per-row softmax state (threads 0..63 own row = tid)
    float m_i = -INFINITY, l_i = 0.f;

    const int ty = tid >> 4, tx = tid & 15;   // S-compute mapping
    const int nkv = qb + 1;                   // causal tile count (BQ==BKV)

    for (int kt = 0; kt < nkv; kt++) {
        const int k0 = kt * BKV;
        __syncthreads();   // previous PV done before overwriting KVs
        for (int e = tid; e < BKV * HD; e += 256) {
            int r = e >> 7, d = e & 127;
            KVs[r][d] = Kbase[(size_t)(k0 + r) * DIM + d];
        }
        __syncthreads();

        // S = Q K^T : 4x4 per thread
        float acc[4][4];
#pragma unroll
        for (int i = 0; i < 4; i++)
#pragma unroll
            for (int j = 0; j < 4; j++) acc[i][j] = 0.f;

#pragma unroll 4
        for (int d = 0; d < HD; d++) {
            float qa[4], kb[4];
#pragma unroll
            for (int i = 0; i < 4; i++) qa[i] = Qs[ty * 4 + i][d];
#pragma unroll
            for (int j = 0; j < 4; j++) kb[j] = KVs[tx * 4 + j][d];
#pragma unroll
            for (int i = 0; i < 4; i++)
#pragma unroll
                for (int j = 0; j < 4; j++)
                    acc[i][j] += qa[i] * kb[j];
        }
#pragma unroll
        for (int i = 0; i < 4; i++)
#pragma unroll
            for (int j = 0; j < 4; j++) {
                int qi = q0 + ty * 4 + i, kj = k0 + tx * 4 + j;
                Ss[ty * 4 + i][tx * 4 + j] = (kj <= qi) ? acc[i][j] : -INFINITY;
            }
        __syncthreads();

        // online softmax per row
        if (tid < BQ) {
            int r = tid;
            float mt = -INFINITY;
#pragma unroll 8
            for (int j = 0; j < BKV; j++) mt = fmaxf(mt, Ss[r][j]);
            float m_new = fmaxf(m_i, mt);
            float corr = __expf(m_i - m_new);
            float sum = 0.f;
#pragma unroll 8
            for (int j = 0; j < BKV; j++) {
                float p = __expf(Ss[r][j] - m_new);
                Ss[r][j] = p;
                sum += p;
            }
            l_i = l_i * corr + sum;
            m_i = m_new;
            rowScale[r] = corr;
            rowSum[r] = l_i;
        }
        __syncthreads();

        // load V into KVs
        for (int e = tid; e < BKV * HD; e += 256) {
            int r = e >> 7, d = e & 127;
            KVs[r][d] = Vbase[(size_t)(k0 + r) * DIM + d];
        }
        __syncthreads();

        // O += P @ V
        float c0 = rowScale[pr * 2], c1 = rowScale[pr * 2 + 1];
#pragma unroll
        for (int d = 0; d < 16; d++) { o0[d] *= c0; o1[d] *= c1; }
        for (int j = 0; j < BKV; j++) {
            float p0 = Ss[pr * 2][j], p1 = Ss[pr * 2 + 1][j];
#pragma unroll
            for (int d = 0; d < 16; d++) {
                float v = KVs[j][dg + d];
                o0[d] += p0 * v;
                o1[d] += p1 * v;
            }
        }
    }
    __syncthreads();

    float inv0 = 1.f / rowSum[pr * 2];
    float inv1 = 1.f / rowSum[pr * 2 + 1];
    float* Obase = O + ((size_t)b * SEQ + q0) * DIM + h * HD;
#pragma unroll
    for (int d = 0; d < 16; d++) {
        Obase[(size_t)(pr * 2)     * DIM + dg + d] = o0[d] * inv0;
        Obase[(size_t)(pr * 2 + 1) * DIM + dg + d] = o1[d] * inv1;
    }
}

// ============================================================
extern "C" void kernel_launch(void* const* d_in, const int* in_sizes, int n_in,
                              void* d_out, int out_size)
{
    const float* x   = (const float*)d_in[0];
    const float* wq  = (const float*)d_in[1];
    const float* wk  = (const float*)d_in[2];
    const float* wv  = (const float*)d_in[3];
    const float* wo  = (const float*)d_in[4];
    const float* fco = (const float*)d_in[5];
    const float* fsi = (const float*)d_in[6];
    float* out = (float*)d_out;

    float *Q, *K, *V, *A;
    cudaGetSymbolAddress((void**)&Q, g_Q);
    cudaGetSymbolAddress((void**)&K, g_K);
    cudaGetSymbolAddress((void**)&V, g_V);
    cudaGetSymbolAddress((void**)&A, g_A);

    cudaFuncSetAttribute(attn_kernel,
        cudaFuncAttributeMaxDynamicSharedMemorySize, ATTN_SMEM_BYTES);

    dim3 ggrid(DIM / BN, MROWS / BM);    // (16, 32)
    sgemm_kernel<<<ggrid, 256>>>(x, wq, Q, MROWS, DIM, DIM);
    sgemm_kernel<<<ggrid, 256>>>(x, wk, K, MROWS, DIM, DIM);
    sgemm_kernel<<<ggrid, 256>>>(x, wv, V, MROWS, DIM, DIM);

    int npairs = MROWS * NH * (HD / 2);
    rope_kernel<<<(npairs + 255) / 256, 256>>>(Q, K, fco, fsi);

    dim3 agrid(SEQ / BQ, NH, BATCH);     // (32, 16, 2)
    attn_kernel<<<agrid, 256, ATTN_SMEM_BYTES>>>(Q, K, V, A);

    sgemm_kernel<<<ggrid, 256>>>(A, wo, out, MROWS, DIM, DIM);
}

// round 2
// speedup vs baseline: 1.4737x; 1.4737x over previous
#include <cuda_runtime.h>
#include <cuda_bf16.h>
#include <math.h>
#include <stdint.h>

#define DIM   2048
#define NH    16
#define HD    128
#define SEQ   2048
#define BATCH 2
#define MROWS (BATCH*SEQ)   // 4096

// ---- scratch (device globals; no allocations allowed) ----
__device__ float g_Q[(size_t)MROWS*DIM];
__device__ float g_K[(size_t)MROWS*DIM];
__device__ float g_V[(size_t)MROWS*DIM];
__device__ float g_A[(size_t)MROWS*DIM];

__device__ __nv_bfloat16 g_Xhi[(size_t)MROWS*DIM];
__device__ __nv_bfloat16 g_Xlo[(size_t)MROWS*DIM];
__device__ __nv_bfloat16 g_Whi[4][(size_t)DIM*DIM];
__device__ __nv_bfloat16 g_Wlo[4][(size_t)DIM*DIM];
__device__ __nv_bfloat16 g_AThi[(size_t)MROWS*DIM];
__device__ __nv_bfloat16 g_ATlo[(size_t)MROWS*DIM];

// ============================================================
// fp32 -> bf16 hi/lo split (vectorized x4)
// ============================================================
__global__ __launch_bounds__(256) void split_kernel(
    const float* __restrict__ in, __nv_bfloat16* __restrict__ hi,
    __nv_bfloat16* __restrict__ lo, int n4)
{
    int i = blockIdx.x * 256 + threadIdx.x;
    if (i >= n4) return;
    float4 v = ((const float4*)in)[i];
    __nv_bfloat16 h0 = __float2bfloat16(v.x);
    __nv_bfloat16 h1 = __float2bfloat16(v.y);
    __nv_bfloat16 h2 = __float2bfloat16(v.z);
    __nv_bfloat16 h3 = __float2bfloat16(v.w);
    __nv_bfloat162 hh0 = __nv_bfloat162(h0, h1);
    __nv_bfloat162 hh1 = __nv_bfloat162(h2, h3);
    __nv_bfloat16 l0 = __float2bfloat16(v.x - __bfloat162float(h0));
    __nv_bfloat16 l1 = __float2bfloat16(v.y - __bfloat162float(h1));
    __nv_bfloat16 l2 = __float2bfloat16(v.z - __bfloat162float(h2));
    __nv_bfloat16 l3 = __float2bfloat16(v.w - __bfloat162float(h3));
    ((__nv_bfloat162*)hi)[2*i]   = hh0;
    ((__nv_bfloat162*)hi)[2*i+1] = hh1;
    ((__nv_bfloat162*)lo)[2*i]   = __nv_bfloat162(l0, l1);
    ((__nv_bfloat162*)lo)[2*i+1] = __nv_bfloat162(l2, l3);
}

// ============================================================
// Tensor-core GEMM: C[M,N] fp32 = (Ahi+Alo)[M,K] @ (Bhi+Blo)[K,N]
// via 3x bf16 mma.sync. 128x128 block, BK=32, 8 warps, double-buffered cp.async.
// ============================================================
#define GBM 128
#define GBN 128
#define GBK 32
#define APAD 40
#define BPAD 136
// smem bytes: Ah,Al: 2*128*40*2 each; Bh,Bl: 2*32*136*2 each
#define GEMM_SMEM (2*(2*GBM*APAD*2) + 2*(2*GBK*BPAD*2))

__device__ __forceinline__ void cp16(uint32_t dst, const void* src) {
    asm volatile("cp.async.cg.shared.global [%0], [%1], 16;\n" :: "r"(dst), "l"(src));
}
__device__ __forceinline__ void ldsm4(uint32_t* r, uint32_t a) {
    asm volatile("ldmatrix.sync.aligned.m8n8.x4.shared.b16 {%0,%1,%2,%3}, [%4];\n"
        : "=r"(r[0]), "=r"(r[1]), "=r"(r[2]), "=r"(r[3]) : "r"(a));
}
__device__ __forceinline__ void ldsm4t(uint32_t* r, uint32_t a) {
    asm volatile("ldmatrix.sync.aligned.m8n8.x4.trans.shared.b16 {%0,%1,%2,%3}, [%4];\n"
        : "=r"(r[0]), "=r"(r[1]), "=r"(r[2]), "=r"(r[3]) : "r"(a));
}
__device__ __forceinline__ void mma16816(float* c, const uint32_t* a, const uint32_t* b) {
    asm volatile("mma.sync.aligned.m16n8k16.row.col.f32.bf16.bf16.f32 "
        "{%0,%1,%2,%3}, {%4,%5,%6,%7}, {%8,%9}, {%0,%1,%2,%3};\n"
        : "+f"(c[0]), "+f"(c[1]), "+f"(c[2]), "+f"(c[3])
        : "r"(a[0]), "r"(a[1]), "r"(a[2]), "r"(a[3]), "r"(b[0]), "r"(b[1]));
}

__global__ __launch_bounds__(256, 1) void gemm_bf16x3(
    const __nv_bfloat16* __restrict__ Ahi, const __nv_bfloat16* __restrict__ Alo,
    const __nv_bfloat16* __restrict__ Bhi, const __nv_bfloat16* __restrict__ Blo,
    float* __restrict__ C, int M, int N, int K)
{
    extern __shared__ char smraw[];
    __nv_bfloat16* sAh = (__nv_bfloat16*)smraw;            // [2][128][APAD]
    __nv_bfloat16* sAl = sAh + 2*GBM*APAD;
    __nv_bfloat16* sBh = sAl + 2*GBM*APAD;                 // [2][32][BPAD]
    __nv_bfloat16* sBl = sBh + 2*GBK*BPAD;

    const uint32_t uAh = (uint32_t)__cvta_generic_to_shared(sAh);
    const uint32_t uAl = (uint32_t)__cvta_generic_to_shared(sAl);
    const uint32_t uBh = (uint32_t)__cvta_generic_to_shared(sBh);
    const uint32_t uBl = (uint32_t)__cvta_generic_to_shared(sBl);

    const int tid  = threadIdx.x;
    const int row0 = blockIdx.y * GBM;
    const int col0 = blockIdx.x * GBN;
    const int warp = tid >> 5, lane = tid & 31;
    const int wm = warp >> 2, wn = warp & 3;      // 2 x 4 warp grid, warp tile 64x32

    float acc[4][4][4];
#pragma unroll
    for (int i = 0; i < 4; i++)
#pragma unroll
        for (int j = 0; j < 4; j++)
#pragma unroll
            for (int r = 0; r < 4; r++) acc[i][j][r] = 0.f;

    const int NK = K / GBK;

    // per-thread load slots
    const int ar0 = tid >> 2,  ak0 = (tid & 3) * 8;        // +64 rows for slot 1
    const int br0 = tid >> 4,  bn0 = (tid & 15) * 8;       // +16 rows for slot 1

#define ISSUE(buf, k0) do {                                                          \
    uint32_t oA = (uint32_t)(buf) * GBM * APAD * 2;                                  \
    uint32_t oB = (uint32_t)(buf) * GBK * BPAD * 2;                                  \
    cp16(uAh + oA + (ar0*APAD + ak0)*2,        Ahi + (size_t)(row0+ar0)*K + (k0)+ak0);      \
    cp16(uAh + oA + ((ar0+64)*APAD + ak0)*2,   Ahi + (size_t)(row0+ar0+64)*K + (k0)+ak0);   \
    cp16(uAl + oA + (ar0*APAD + ak0)*2,        Alo + (size_t)(row0+ar0)*K + (k0)+ak0);      \
    cp16(uAl + oA + ((ar0+64)*APAD + ak0)*2,   Alo + (size_t)(row0+ar0+64)*K + (k0)+ak0);   \
    cp16(uBh + oB + (br0*BPAD + bn0)*2,        Bhi + (size_t)((k0)+br0)*N + col0+bn0);      \
    cp16(uBh + oB + ((br0+16)*BPAD + bn0)*2,   Bhi + (size_t)((k0)+br0+16)*N + col0+bn0);   \
    cp16(uBl + oB + (br0*BPAD + bn0)*2,        Blo + (size_t)((k0)+br0)*N + col0+bn0);      \
    cp16(uBl + oB + ((br0+16)*BPAD + bn0)*2,   Blo + (size_t)((k0)+br0+16)*N + col0+bn0);   \
} while (0)

    ISSUE(0, 0);
    asm volatile("cp.async.commit_group;\n");

    for (int kc = 0; kc < NK; kc++) {
        if (kc + 1 < NK) {
            ISSUE((kc + 1) & 1, (kc + 1) * GBK);
            asm volatile("cp.async.commit_group;\n");
            asm volatile("cp.async.wait_group 1;\n");
        } else {
            asm volatile("cp.async.wait_group 0;\n");
        }
        __syncthreads();

        const int buf = kc & 1;
        const uint32_t bAh = uAh + (uint32_t)buf * GBM * APAD * 2;
        const uint32_t bAl = uAl + (uint32_t)buf * GBM * APAD * 2;
        const uint32_t bBh = uBh + (uint32_t)buf * GBK * BPAD * 2;
        const uint32_t bBl = uBl + (uint32_t)buf * GBK * BPAD * 2;

#pragma unroll
        for (int ks = 0; ks < 2; ks++) {
            uint32_t ah[4][4], al[4][4];
            const int arow = (lane & 7) + ((lane >> 3) & 1) * 8;
            const int acol = ks * 16 + (lane >> 4) * 8;
#pragma unroll
            for (int mt = 0; mt < 4; mt++) {
                int r = wm * 64 + mt * 16 + arow;
                ldsm4(ah[mt], bAh + (r * APAD + acol) * 2);
                ldsm4(al[mt], bAl + (r * APAD + acol) * 2);
            }
            uint32_t bh[4][2], bl[4][2];
            const int brow = ks * 16 + (lane & 7) + ((lane >> 3) & 1) * 8;
#pragma unroll
            for (int hh = 0; hh < 2; hh++) {
                int nc = wn * 32 + hh * 16 + (lane >> 4) * 8;
                uint32_t t4[4];
                ldsm4t(t4, bBh + (brow * BPAD + nc) * 2);
                bh[hh*2][0] = t4[0]; bh[hh*2][1] = t4[1];
                bh[hh*2+1][0] = t4[2]; bh[hh*2+1][1] = t4[3];
                ldsm4t(t4, bBl + (brow * BPAD + nc) * 2);
                bl[hh*2][0] = t4[0]; bl[hh*2][1] = t4[1];
                bl[hh*2+1][0] = t4[2]; bl[hh*2+1][1] = t4[3];
            }
#pragma unroll
            for (int mt = 0; mt < 4; mt++)
#pragma unroll
                for (int nt = 0; nt < 4; nt++) {
                    mma16816(acc[mt][nt], ah[mt], bh[nt]);
                    mma16816(acc[mt][nt], ah[mt], bl[nt]);
                    mma16816(acc[mt][nt], al[mt], bh[nt]);
                }
        }
        __syncthreads();
    }

    // epilogue
#pragma unroll
    for (int mt = 0; mt < 4; mt++) {
#pragma unroll
        for (int nt = 0; nt < 4; nt++) {
            int r = row0 + wm * 64 + mt * 16 + (lane >> 2);
            int c = col0 + wn * 32 + nt * 8 + (lane & 3) * 2;
            float2 v0 = make_float2(acc[mt][nt][0], acc[mt][nt][1]);
            float2 v1 = make_float2(acc[mt][nt][2], acc[mt][nt][3]);
            *(float2*)(C + (size_t)r * N + c)       = v0;
            *(float2*)(C + (size_t)(r + 8) * N + c) = v1;
        }
    }
}

// ============================================================
// RoPE on Q and K (in place). Q additionally pre-scaled by 1/sqrt(HD).
// ============================================================
__global__ __launch_bounds__(256) void rope_kernel(
    float* __restrict__ Q, float* __restrict__ K,
    const float* __restrict__ fcos, const float* __restrict__ fsin)
{
    const int half = HD / 2;
    int idx = blockIdx.x * blockDim.x + threadIdx.x;
    if (idx >= MROWS * NH * half) return;
    int i   = idx % half;
    int tmp = idx / half;
    int h   = tmp % NH;
    int rs  = tmp / NH;
    int s   = rs % SEQ;

    float c  = fcos[s * half + i];
    float sn = fsin[s * half + i];
    size_t base = (size_t)rs * DIM + h * HD + 2 * i;

    const float qscale = 0.08838834764831845f;
    float q0 = Q[base], q1 = Q[base + 1];
    Q[base]     = (q0 * c - q1 * sn) * qscale;
    Q[base + 1] = (q0 * sn + q1 * c) * qscale;
    float k0 = K[base], k1 = K[base + 1];
    K[base]     = k0 * c - k1 * sn;
    K[base + 1] = k0 * sn + k1 * c;
}

// ============================================================
// Causal flash attention, fp32. 64x64 tiles, Hd=128, 256 threads.
// ============================================================
#define BQ  64
#define BKV 64
#define QPAD (HD + 1)
#define SPAD (BKV + 1)
#define ATTN_SMEM_FLOATS (2 * BQ * QPAD + BQ * SPAD + 2 * BQ)
#define ATTN_SMEM_BYTES  (ATTN_SMEM_FLOATS * 4)

__global__ __launch_bounds__(256) void attn_kernel(
    const float* __restrict__ Q, const float* __restrict__ K,
    const float* __restrict__ V, float* __restrict__ O)
{
    extern __shared__ float sm[];
    float (*Qs)[QPAD]  = (float(*)[QPAD])sm;
    float (*KVs)[QPAD] = (float(*)[QPAD])(sm + BQ * QPAD);
    float (*Ss)[SPAD]  = (float(*)[SPAD])(sm + 2 * BQ * QPAD);
    float* rowScale    = sm + 2 * BQ * QPAD + BQ * SPAD;
    float* rowSum      = rowScale + BQ;

    const int tid = threadIdx.x;
    const int qb = blockIdx.x, h = blockIdx.y, b = blockIdx.z;
    const int q0 = qb * BQ;

    const float* Qbase = Q + (size_t)b * SEQ * DIM + h * HD;
    const float* Kbase = K + (size_t)b * SEQ * DIM + h * HD;
    const float* Vbase = V + (size_t)b * SEQ * DIM + h * HD;

    for (int e = tid; e < BQ * HD; e += 256) {
        int r = e >> 7, d = e & 127;
        Qs[r][d] = Qbase[(size_t)(q0 + r) * DIM + d];
    }

    const int pr = tid >> 3;
    const int dg = (tid & 7) * 16;
    float o0[16], o1[16];
#pragma unroll
    for (int d = 0; d < 16; d++) { o0[d] = 0.f; o1[d] = 0.f; }

    float m_i = -INFINITY, l_i = 0.f;

    const int ty = tid >> 4, tx = tid & 15;
    const int nkv = qb + 1;

    for (int kt = 0; kt < nkv; kt++) {
        const int k0 = kt * BKV;
        __syncthreads();
        for (int e = tid; e < BKV * HD; e += 256) {
            int r = e >> 7, d = e & 127;
            KVs[r][d] = Kbase[(size_t)(k0 + r) * DIM + d];
        }
        __syncthreads();

        float acc[4][4];
#pragma unroll
        for (int i = 0; i < 4; i++)
#pragma unroll
            for (int j = 0; j < 4; j++) acc[i][j] = 0.f;

#pragma unroll 4
        for (int d = 0; d < HD; d++) {
            float qa[4], kb[4];
#pragma unroll
            for (int i = 0; i < 4; i++) qa[i] = Qs[ty * 4 + i][d];
#pragma unroll
            for (int j = 0; j < 4; j++) kb[j] = KVs[tx * 4 + j][d];
#pragma unroll
            for (int i = 0; i < 4; i++)
#pragma unroll
                for (int j = 0; j < 4; j++)
                    acc[i][j] += qa[i] * kb[j];
        }
#pragma unroll
        for (int i = 0; i < 4; i++)
#pragma unroll
            for (int j = 0; j < 4; j++) {
                int qi = q0 + ty * 4 + i, kj = k0 + tx * 4 + j;
                Ss[ty * 4 + i][tx * 4 + j] = (kj <= qi) ? acc[i][j] : -INFINITY;
            }
        __syncthreads();

        if (tid < BQ) {
            int r = tid;
            float mt = -INFINITY;
#pragma unroll 8
            for (int j = 0; j < BKV; j++) mt = fmaxf(mt, Ss[r][j]);
            float m_new = fmaxf(m_i, mt);
            float corr = __expf(m_i - m_new);
            float sum = 0.f;
#pragma unroll 8
            for (int j = 0; j < BKV; j++) {
                float p = __expf(Ss[r][j] - m_new);
                Ss[r][j] = p;
                sum += p;
            }
            l_i = l_i * corr + sum;
            m_i = m_new;
            rowScale[r] = corr;
            rowSum[r] = l_i;
        }
        __syncthreads();

        for (int e = tid; e < BKV * HD; e += 256) {
            int r = e >> 7, d = e & 127;
            KVs[r][d] = Vbase[(size_t)(k0 + r) * DIM + d];
        }
        __syncthreads();

        float c0 = rowScale[pr * 2], c1 = rowScale[pr * 2 + 1];
#pragma unroll
        for (int d = 0; d < 16; d++) { o0[d] *= c0; o1[d] *= c1; }
        for (int j = 0; j < BKV; j++) {
            float p0 = Ss[pr * 2][j], p1 = Ss[pr * 2 + 1][j];
#pragma unroll
            for (int d = 0; d < 16; d++) {
                float v = KVs[j][dg + d];
                o0[d] += p0 * v;
                o1[d] += p1 * v;
            }
        }
    }
    __syncthreads();

    float inv0 = 1.f / rowSum[pr * 2];
    float inv1 = 1.f / rowSum[pr * 2 + 1];
    float* Obase = O + ((size_t)b * SEQ + q0) * DIM + h * HD;
#pragma unroll
    for (int d = 0; d < 16; d++) {
        Obase[(size_t)(pr * 2)     * DIM + dg + d] = o0[d] * inv0;
        Obase[(size_t)(pr * 2 + 1) * DIM + dg + d] = o1[d] * inv1;
    }
}

// ============================================================
extern "C" void kernel_launch(void* const* d_in, const int* in_sizes, int n_in,
                              void* d_out, int out_size)
{
    const float* x   = (const float*)d_in[0];
    const float* wq  = (const float*)d_in[1];
    const float* wk  = (const float*)d_in[2];
    const float* wv  = (const float*)d_in[3];
    const float* wo  = (const float*)d_in[4];
    const float* fco = (const float*)d_in[5];
    const float* fsi = (const float*)d_in[6];
    float* out = (float*)d_out;

    float *Q, *K, *V, *A;
    __nv_bfloat16 *Xhi, *Xlo, *Whi, *Wlo, *AThi, *ATlo;
    cudaGetSymbolAddress((void**)&Q, g_Q);
    cudaGetSymbolAddress((void**)&K, g_K);
    cudaGetSymbolAddress((void**)&V, g_V);
    cudaGetSymbolAddress((void**)&A, g_A);
    cudaGetSymbolAddress((void**)&Xhi, g_Xhi);
    cudaGetSymbolAddress((void**)&Xlo, g_Xlo);
    cudaGetSymbolAddress((void**)&Whi, g_Whi);
    cudaGetSymbolAddress((void**)&Wlo, g_Wlo);
    cudaGetSymbolAddress((void**)&AThi, g_AThi);
    cudaGetSymbolAddress((void**)&ATlo, g_ATlo);

    cudaFuncSetAttribute(attn_kernel,
        cudaFuncAttributeMaxDynamicSharedMemorySize, ATTN_SMEM_BYTES);
    cudaFuncSetAttribute(gemm_bf16x3,
        cudaFuncAttributeMaxDynamicSharedMemorySize, GEMM_SMEM);

    const int nX4 = MROWS * DIM / 4;     // 2,097,152
    const int nW4 = DIM * DIM / 4;       // 1,048,576
    const size_t WSZ = (size_t)DIM * DIM;

    split_kernel<<<(nX4 + 255)/256, 256>>>(x,  Xhi, Xlo, nX4);
    split_kernel<<<(nW4 + 255)/256, 256>>>(wq, Whi + 0*WSZ, Wlo + 0*WSZ, nW4);
    split_kernel<<<(nW4 + 255)/256, 256>>>(wk, Whi + 1*WSZ, Wlo + 1*WSZ, nW4);
    split_kernel<<<(nW4 + 255)/256, 256>>>(wv, Whi + 2*WSZ, Wlo + 2*WSZ, nW4);
    split_kernel<<<(nW4 + 255)/256, 256>>>(wo, Whi + 3*WSZ, Wlo + 3*WSZ, nW4);

    dim3 ggrid(DIM / GBN, MROWS / GBM);  // (16, 32)
    gemm_bf16x3<<<ggrid, 256, GEMM_SMEM>>>(Xhi, Xlo, Whi + 0*WSZ, Wlo + 0*WSZ, Q, MROWS, DIM, DIM);
    gemm_bf16x3<<<ggrid, 256, GEMM_SMEM>>>(Xhi, Xlo, Whi + 1*WSZ, Wlo + 1*WSZ, K, MROWS, DIM, DIM);
    gemm_bf16x3<<<ggrid, 256, GEMM_SMEM>>>(Xhi, Xlo, Whi + 2*WSZ, Wlo + 2*WSZ, V, MROWS, DIM, DIM);

    int npairs = MROWS * NH * (HD / 2);
    rope_kernel<<<(npairs + 255) / 256, 256>>>(Q, K, fco, fsi);

    dim3 agrid(SEQ / BQ, NH, BATCH);     // (32, 16, 2)
    attn_kernel<<<agrid, 256, ATTN_SMEM_BYTES>>>(Q, K, V, A);

    split_kernel<<<(nX4 + 255)/256, 256>>>(A, AThi, ATlo, nX4);
    gemm_bf16x3<<<ggrid, 256, GEMM_SMEM>>>(AThi, ATlo, Whi + 3*WSZ, Wlo + 3*WSZ, out, MROWS, DIM, DIM);
}

// round 3
// speedup vs baseline: 3.9445x; 2.6765x over previous
#include <cuda_runtime.h>
#include <cuda_bf16.h>
#include <math.h>
#include <stdint.h>

#define DIM   2048
#define NH    16
#define HD    128
#define SEQ   2048
#define BATCH 2
#define MROWS (BATCH*SEQ)   // 4096

// ---- scratch (device globals) ----
__device__ float g_Q[(size_t)MROWS*DIM];
__device__ float g_K[(size_t)MROWS*DIM];
__device__ float g_V[(size_t)MROWS*DIM];

__device__ __nv_bfloat16 g_Xhi[(size_t)MROWS*DIM];
__device__ __nv_bfloat16 g_Xlo[(size_t)MROWS*DIM];
__device__ __nv_bfloat16 g_Whi[4][(size_t)DIM*DIM];
__device__ __nv_bfloat16 g_Wlo[4][(size_t)DIM*DIM];
__device__ __nv_bfloat16 g_Qhi[(size_t)MROWS*DIM];
__device__ __nv_bfloat16 g_Qlo[(size_t)MROWS*DIM];
__device__ __nv_bfloat16 g_Khi[(size_t)MROWS*DIM];
__device__ __nv_bfloat16 g_Klo[(size_t)MROWS*DIM];
__device__ __nv_bfloat16 g_Vhi[(size_t)MROWS*DIM];
__device__ __nv_bfloat16 g_Vlo[(size_t)MROWS*DIM];
__device__ __nv_bfloat16 g_AThi[(size_t)MROWS*DIM];
__device__ __nv_bfloat16 g_ATlo[(size_t)MROWS*DIM];

// ---------- common PTX helpers ----------
__device__ __forceinline__ void cp16(uint32_t dst, const void* src) {
    asm volatile("cp.async.cg.shared.global [%0], [%1], 16;\n" :: "r"(dst), "l"(src));
}
__device__ __forceinline__ void ldsm4(uint32_t* r, uint32_t a) {
    asm volatile("ldmatrix.sync.aligned.m8n8.x4.shared.b16 {%0,%1,%2,%3}, [%4];\n"
        : "=r"(r[0]), "=r"(r[1]), "=r"(r[2]), "=r"(r[3]) : "r"(a));
}
__device__ __forceinline__ void ldsm4t(uint32_t* r, uint32_t a) {
    asm volatile("ldmatrix.sync.aligned.m8n8.x4.trans.shared.b16 {%0,%1,%2,%3}, [%4];\n"
        : "=r"(r[0]), "=r"(r[1]), "=r"(r[2]), "=r"(r[3]) : "r"(a));
}
__device__ __forceinline__ void mma16816(float* c, const uint32_t* a, const uint32_t* b) {
    asm volatile("mma.sync.aligned.m16n8k16.row.col.f32.bf16.bf16.f32 "
        "{%0,%1,%2,%3}, {%4,%5,%6,%7}, {%8,%9}, {%0,%1,%2,%3};\n"
        : "+f"(c[0]), "+f"(c[1]), "+f"(c[2]), "+f"(c[3])
        : "r"(a[0]), "r"(a[1]), "r"(a[2]), "r"(a[3]), "r"(b[0]), "r"(b[1]));
}
__device__ __forceinline__ uint32_t packbf(float x, float y) {
    __nv_bfloat162 t(__float2bfloat16(x), __float2bfloat16(y));
    return *(uint32_t*)&t;
}
__device__ __forceinline__ void split2(float x, float y, uint32_t& hi, uint32_t& lo) {
    float hx = __bfloat162float(__float2bfloat16(x));
    float hy = __bfloat162float(__float2bfloat16(y));
    hi = packbf(hx, hy);
    lo = packbf(x - hx, y - hy);
}

// ============================================================
// fp32 -> bf16 hi/lo split (vectorized x4)
// ============================================================
__global__ __launch_bounds__(256) void split_kernel(
    const float* __restrict__ in, __nv_bfloat16* __restrict__ hi,
    __nv_bfloat16* __restrict__ lo, int n4)
{
    int i = blockIdx.x * 256 + threadIdx.x;
    if (i >= n4) return;
    float4 v = ((const float4*)in)[i];
    uint32_t h0, l0, h1, l1;
    split2(v.x, v.y, h0, l0);
    split2(v.z, v.w, h1, l1);
    ((uint32_t*)hi)[2*i]   = h0;
    ((uint32_t*)hi)[2*i+1] = h1;
    ((uint32_t*)lo)[2*i]   = l0;
    ((uint32_t*)lo)[2*i+1] = l1;
}

// ============================================================
// Tensor-core GEMM (bf16x3): C fp32 = (Ahi+Alo) @ (Bhi+Blo)
// ============================================================
#define GBM 128
#define GBN 128
#define GBK 32
#define APAD 40
#define BPAD 136
#define GEMM_SMEM (2*(2*GBM*APAD*2) + 2*(2*GBK*BPAD*2))

__global__ __launch_bounds__(256, 1) void gemm_bf16x3(
    const __nv_bfloat16* __restrict__ Ahi, const __nv_bfloat16* __restrict__ Alo,
    const __nv_bfloat16* __restrict__ Bhi, const __nv_bfloat16* __restrict__ Blo,
    float* __restrict__ C, int M, int N, int K)
{
    extern __shared__ char smraw[];
    __nv_bfloat16* sAh = (__nv_bfloat16*)smraw;
    __nv_bfloat16* sAl = sAh + 2*GBM*APAD;
    __nv_bfloat16* sBh = sAl + 2*GBM*APAD;
    __nv_bfloat16* sBl = sBh + 2*GBK*BPAD;

    const uint32_t uAh = (uint32_t)__cvta_generic_to_shared(sAh);
    const uint32_t uAl = (uint32_t)__cvta_generic_to_shared(sAl);
    const uint32_t uBh = (uint32_t)__cvta_generic_to_shared(sBh);
    const uint32_t uBl = (uint32_t)__cvta_generic_to_shared(sBl);

    const int tid  = threadIdx.x;
    const int row0 = blockIdx.y * GBM;
    const int col0 = blockIdx.x * GBN;
    const int warp = tid >> 5, lane = tid & 31;
    const int wm = warp >> 2, wn = warp & 3;

    float acc[4][4][4];
#pragma unroll
    for (int i = 0; i < 4; i++)
#pragma unroll
        for (int j = 0; j < 4; j++)
#pragma unroll
            for (int r = 0; r < 4; r++) acc[i][j][r] = 0.f;

    const int NK = K / GBK;
    const int ar0 = tid >> 2,  ak0 = (tid & 3) * 8;
    const int br0 = tid >> 4,  bn0 = (tid & 15) * 8;

#define ISSUE(buf, k0) do {                                                          \
    uint32_t oA = (uint32_t)(buf) * GBM * APAD * 2;                                  \
    uint32_t oB = (uint32_t)(buf) * GBK * BPAD * 2;                                  \
    cp16(uAh + oA + (ar0*APAD + ak0)*2,        Ahi + (size_t)(row0+ar0)*K + (k0)+ak0);      \
    cp16(uAh + oA + ((ar0+64)*APAD + ak0)*2,   Ahi + (size_t)(row0+ar0+64)*K + (k0)+ak0);   \
    cp16(uAl + oA + (ar0*APAD + ak0)*2,        Alo + (size_t)(row0+ar0)*K + (k0)+ak0);      \
    cp16(uAl + oA + ((ar0+64)*APAD + ak0)*2,   Alo + (size_t)(row0+ar0+64)*K + (k0)+ak0);   \
    cp16(uBh + oB + (br0*BPAD + bn0)*2,        Bhi + (size_t)((k0)+br0)*N + col0+bn0);      \
    cp16(uBh + oB + ((br0+16)*BPAD + bn0)*2,   Bhi + (size_t)((k0)+br0+16)*N + col0+bn0);   \
    cp16(uBl + oB + (br0*BPAD + bn0)*2,        Blo + (size_t)((k0)+br0)*N + col0+bn0);      \
    cp16(uBl + oB + ((br0+16)*BPAD + bn0)*2,   Blo + (size_t)((k0)+br0+16)*N + col0+bn0);   \
} while (0)

    ISSUE(0, 0);
    asm volatile("cp.async.commit_group;\n");

    for (int kc = 0; kc < NK; kc++) {
        if (kc + 1 < NK) {
            ISSUE((kc + 1) & 1, (kc + 1) * GBK);
            asm volatile("cp.async.commit_group;\n");
            asm volatile("cp.async.wait_group 1;\n");
        } else {
            asm volatile("cp.async.wait_group 0;\n");
        }
        __syncthreads();

        const int buf = kc & 1;
        const uint32_t bAh = uAh + (uint32_t)buf * GBM * APAD * 2;
        const uint32_t bAl = uAl + (uint32_t)buf * GBM * APAD * 2;
        const uint32_t bBh = uBh + (uint32_t)buf * GBK * BPAD * 2;
        const uint32_t bBl = uBl + (uint32_t)buf * GBK * BPAD * 2;

#pragma unroll
        for (int ks = 0; ks < 2; ks++) {
            uint32_t ah[4][4], al[4][4];
            const int arow = (lane & 7) + ((lane >> 3) & 1) * 8;
            const int acol = ks * 16 + (lane >> 4) * 8;
#pragma unroll
            for (int mt = 0; mt < 4; mt++) {
                int r = wm * 64 + mt * 16 + arow;
                ldsm4(ah[mt], bAh + (r * APAD + acol) * 2);
                ldsm4(al[mt], bAl + (r * APAD + acol) * 2);
            }
            uint32_t bh[4][2], bl[4][2];
            const int brow = ks * 16 + (lane & 7) + ((lane >> 3) & 1) * 8;
#pragma unroll
            for (int hh = 0; hh < 2; hh++) {
                int nc = wn * 32 + hh * 16 + (lane >> 4) * 8;
                uint32_t t4[4];
                ldsm4t(t4, bBh + (brow * BPAD + nc) * 2);
                bh[hh*2][0] = t4[0]; bh[hh*2][1] = t4[1];
                bh[hh*2+1][0] = t4[2]; bh[hh*2+1][1] = t4[3];
                ldsm4t(t4, bBl + (brow * BPAD + nc) * 2);
                bl[hh*2][0] = t4[0]; bl[hh*2][1] = t4[1];
                bl[hh*2+1][0] = t4[2]; bl[hh*2+1][1] = t4[3];
            }
#pragma unroll
            for (int mt = 0; mt < 4; mt++)
#pragma unroll
                for (int nt = 0; nt < 4; nt++) {
                    mma16816(acc[mt][nt], ah[mt], bh[nt]);
                    mma16816(acc[mt][nt], ah[mt], bl[nt]);
                    mma16816(acc[mt][nt], al[mt], bh[nt]);
                }
        }
        __syncthreads();
    }

#pragma unroll
    for (int mt = 0; mt < 4; mt++) {
#pragma unroll
        for (int nt = 0; nt < 4; nt++) {
            int r = row0 + wm * 64 + mt * 16 + (lane >> 2);
            int c = col0 + wn * 32 + nt * 8 + (lane & 3) * 2;
            *(float2*)(C + (size_t)r * N + c)       = make_float2(acc[mt][nt][0], acc[mt][nt][1]);
            *(float2*)(C + (size_t)(r + 8) * N + c) = make_float2(acc[mt][nt][2], acc[mt][nt][3]);
        }
    }
}

// ============================================================
// RoPE + bf16 hi/lo split for Q (scaled by 1/sqrt(HD)) and K
// ============================================================
__global__ __launch_bounds__(256) void rope_split_kernel(
    const float* __restrict__ Q, const float* __restrict__ K,
    const float* __restrict__ fcos, const float* __restrict__ fsin,
    __nv_bfloat16* __restrict__ Qhi, __nv_bfloat16* __restrict__ Qlo,
    __nv_bfloat16* __restrict__ Khi, __nv_bfloat16* __restrict__ Klo)
{
    const int half = HD / 2;
    int idx = blockIdx.x * blockDim.x + threadIdx.x;
    if (idx >= MROWS * NH * half) return;
    int i   = idx % half;
    int tmp = idx / half;
    int h   = tmp % NH;
    int rs  = tmp / NH;
    int s   = rs % SEQ;

    float c  = fcos[s * half + i];
    float sn = fsin[s * half + i];
    size_t base = (size_t)rs * DIM + h * HD + 2 * i;

    const float qscale = 0.08838834764831845f;
    float q0 = Q[base], q1 = Q[base + 1];
    float qo0 = (q0 * c - q1 * sn) * qscale;
    float qo1 = (q0 * sn + q1 * c) * qscale;
    float k0 = K[base], k1 = K[base + 1];
    float ko0 = k0 * c - k1 * sn;
    float ko1 = k0 * sn + k1 * c;

    uint32_t hq, lq, hk, lk;
    split2(qo0, qo1, hq, lq);
    split2(ko0, ko1, hk, lk);
    *(uint32_t*)(Qhi + base) = hq;
    *(uint32_t*)(Qlo + base) = lq;
    *(uint32_t*)(Khi + base) = hk;
    *(uint32_t*)(Klo + base) = lk;
}

// ============================================================
// Tensor-core causal flash attention (bf16x3), 64x64 tiles.
// 4 warps; warp w owns Q rows w*16..w*16+15 of the 64-row tile.
// Output written directly as bf16 hi/lo for the O-projection GEMM.
// ============================================================
#define AQ  64
#define APD 136
#define TILE_E (AQ*APD)                 // elements per smem matrix
#define ATTN_SMEM (6*TILE_E*2)          // Qh,Ql,Kh,Kl,Vh,Vl

__global__ __launch_bounds__(128) void attn_tc_kernel(
    const __nv_bfloat16* __restrict__ Qhi, const __nv_bfloat16* __restrict__ Qlo,
    const __nv_bfloat16* __restrict__ Khi, const __nv_bfloat16* __restrict__ Klo,
    const __nv_bfloat16* __restrict__ Vhi, const __nv_bfloat16* __restrict__ Vlo,
    __nv_bfloat16* __restrict__ Ohi, __nv_bfloat16* __restrict__ Olo)
{
    extern __shared__ __nv_bfloat16 sm[];
    __nv_bfloat16* sQh = sm;
    __nv_bfloat16* sQl = sQh + TILE_E;
    __nv_bfloat16* sKh = sQl + TILE_E;
    __nv_bfloat16* sKl = sKh + TILE_E;
    __nv_bfloat16* sVh = sKl + TILE_E;
    __nv_bfloat16* sVl = sVh + TILE_E;
    const uint32_t uQh = (uint32_t)__cvta_generic_to_shared(sQh);
    const uint32_t uQl = (uint32_t)__cvta_generic_to_shared(sQl);
    const uint32_t uKh = (uint32_t)__cvta_generic_to_shared(sKh);
    const uint32_t uKl = (uint32_t)__cvta_generic_to_shared(sKl);
    const uint32_t uVh = (uint32_t)__cvta_generic_to_shared(sVh);
    const uint32_t uVl = (uint32_t)__cvta_generic_to_shared(sVl);

    const int tid = threadIdx.x, warp = tid >> 5, lane = tid & 31;
    const int qt = (int)(gridDim.x - 1 - blockIdx.x);   // heavy tiles first
    const int h = blockIdx.y, b = blockIdx.z;
    const int q0 = qt * AQ;
    const size_t rowbase = (size_t)b * SEQ;
    const size_t colh = (size_t)h * HD;

    // tile loader: 64 rows x 128 bf16 -> 1024 16B chunks, 8 per thread
#define LOADTILE(dstu, src, r0) do {                                           \
    for (int c0_ = tid; c0_ < 1024; c0_ += 128) {                              \
        int r_ = c0_ >> 4, o_ = (c0_ & 15) * 8;                                \
        cp16((dstu) + (r_*APD + o_)*2,                                         \
             (src) + (rowbase + (r0) + r_)*DIM + colh + o_);                   \
    } } while (0)

    LOADTILE(uQh, Qhi, q0);
    LOADTILE(uQl, Qlo, q0);
    LOADTILE(uKh, Khi, 0);
    LOADTILE(uKl, Klo, 0);
    asm volatile("cp.async.commit_group;\n");

    float o[16][4];
#pragma unroll
    for (int nt = 0; nt < 16; nt++)
#pragma unroll
        for (int r = 0; r < 4; r++) o[nt][r] = 0.f;
    float m0 = -INFINITY, m1 = -INFINITY, l0 = 0.f, l1 = 0.f;

    const int nkv = qt + 1;
    const int arow = (lane & 7) + ((lane >> 3) & 1) * 8;
    const int acol8 = (lane >> 4) * 8;
    const int bro8 = (lane & 7) + ((lane >> 4) << 3);   // B-frag row (non-trans, K)
    const int bco8 = ((lane >> 3) & 1) * 8;             // B-frag col offset
    const int vro8 = (lane & 7) + ((lane >> 3) & 1) * 8; // trans ldsm row (V)
    const int vco8 = (lane >> 4) * 8;

    for (int kt = 0; kt < nkv; kt++) {
        asm volatile("cp.async.wait_group 0;\n");
        __syncthreads();

        // prefetch V(kt) while computing S
        LOADTILE(uVh, Vhi, kt*AQ);
        LOADTILE(uVl, Vlo, kt*AQ);
        asm volatile("cp.async.commit_group;\n");

        // ---- S = Q K^T (bf16x3) ----
        float s[8][4];
#pragma unroll
        for (int t = 0; t < 8; t++)
#pragma unroll
            for (int r = 0; r < 4; r++) s[t][r] = 0.f;

#pragma unroll
        for (int ks = 0; ks < 8; ks++) {
            uint32_t qh4[4], ql4[4];
            uint32_t aoff = ((warp*16 + arow)*APD + ks*16 + acol8)*2;
            ldsm4(qh4, uQh + aoff);
            ldsm4(ql4, uQl + aoff);
#pragma unroll
            for (int bt = 0; bt < 4; bt++) {
                uint32_t kh4[4], kl4[4];
                uint32_t boff = ((bt*16 + bro8)*APD + ks*16 + bco8)*2;
                ldsm4(kh4, uKh + boff);
                ldsm4(kl4, uKl + boff);
                mma16816(s[2*bt],   qh4, kh4);
                mma16816(s[2*bt],   qh4, kl4);
                mma16816(s[2*bt],   ql4, kh4);
                mma16816(s[2*bt+1], qh4, kh4+2);
                mma16816(s[2*bt+1], qh4, kl4+2);
                mma16816(s[2*bt+1], ql4, kh4+2);
            }
        }

        // ---- causal mask on diagonal tile ----
        if (kt == qt) {
            int rl0 = warp*16 + (lane >> 2);
            int cb = (lane & 3) * 2;
#pragma unroll
            for (int t = 0; t < 8; t++) {
                int c0 = t*8 + cb, c1 = c0 + 1;
                if (c0 > rl0)     s[t][0] = -INFINITY;
                if (c1 > rl0)     s[t][1] = -INFINITY;
                if (c0 > rl0 + 8) s[t][2] = -INFINITY;
                if (c1 > rl0 + 8) s[t][3] = -INFINITY;
            }
        }

        // ---- online softmax (register-resident) ----
        float mt0 = -INFINITY, mt1 = -INFINITY;
#pragma unroll
        for (int t = 0; t < 8; t++) {
            mt0 = fmaxf(mt0, fmaxf(s[t][0], s[t][1]));
            mt1 = fmaxf(mt1, fmaxf(s[t][2], s[t][3]));
        }
        mt0 = fmaxf(mt0, __shfl_xor_sync(0xffffffffu, mt0, 1));
        mt0 = fmaxf(mt0, __shfl_xor_sync(0xffffffffu, mt0, 2));
        mt1 = fmaxf(mt1, __shfl_xor_sync(0xffffffffu, mt1, 1));
        mt1 = fmaxf(mt1, __shfl_xor_sync(0xffffffffu, mt1, 2));
        float mn0 = fmaxf(m0, mt0), mn1 = fmaxf(m1, mt1);
        float corr0 = __expf(m0 - mn0), corr1 = __expf(m1 - mn1);
        m0 = mn0; m1 = mn1;

        float p[8][4];
        float sum0 = 0.f, sum1 = 0.f;
#pragma unroll
        for (int t = 0; t < 8; t++) {
            p[t][0] = __expf(s[t][0] - mn0);
            p[t][1] = __expf(s[t][1] - mn0);
            p[t][2] = __expf(s[t][2] - mn1);
            p[t][3] = __expf(s[t][3] - mn1);
            sum0 += p[t][0] + p[t][1];
            sum1 += p[t][2] + p[t][3];
        }
        sum0 += __shfl_xor_sync(0xffffffffu, sum0, 1);
        sum0 += __shfl_xor_sync(0xffffffffu, sum0, 2);
        sum1 += __shfl_xor_sync(0xffffffffu, sum1, 1);
        sum1 += __shfl_xor_sync(0xffffffffu, sum1, 2);
        l0 = l0 * corr0 + sum0;
        l1 = l1 * corr1 + sum1;

        // repack P into A fragments (hi/lo)
        uint32_t ph[4][4], pl[4][4];
#pragma unroll
        for (int c = 0; c < 4; c++) {
            split2(p[2*c][0],   p[2*c][1],   ph[c][0], pl[c][0]);
            split2(p[2*c][2],   p[2*c][3],   ph[c][1], pl[c][1]);
            split2(p[2*c+1][0], p[2*c+1][1], ph[c][2], pl[c][2]);
            split2(p[2*c+1][2], p[2*c+1][3], ph[c][3], pl[c][3]);
        }

        // rescale O
#pragma unroll
        for (int nt = 0; nt < 16; nt++) {
            o[nt][0] *= corr0; o[nt][1] *= corr0;
            o[nt][2] *= corr1; o[nt][3] *= corr1;
        }

        asm volatile("cp.async.wait_group 0;\n");   // V(kt) ready
        __syncthreads();

        // prefetch K(kt+1) while computing PV
        if (kt + 1 < nkv) {
            LOADTILE(uKh, Khi, (kt+1)*AQ);
            LOADTILE(uKl, Klo, (kt+1)*AQ);
        }
        asm volatile("cp.async.commit_group;\n");

        // ---- O += P V (bf16x3) ----
#pragma unroll
        for (int c = 0; c < 4; c++) {
#pragma unroll
            for (int np = 0; np < 8; np++) {
                uint32_t vh4[4], vl4[4];
                uint32_t voff = ((c*16 + vro8)*APD + np*16 + vco8)*2;
                ldsm4t(vh4, uVh + voff);
                ldsm4t(vl4, uVl + voff);
                mma16816(o[2*np],   ph[c], vh4);
                mma16816(o[2*np],   ph[c], vl4);
                mma16816(o[2*np],   pl[c], vh4);
                mma16816(o[2*np+1], ph[c], vh4+2);
                mma16816(o[2*np+1], ph[c], vl4+2);
                mma16816(o[2*np+1], pl[c], vh4+2);
            }
        }
    }

    // ---- finalize: divide by l, write bf16 hi/lo ----
    float inv0 = 1.f / l0, inv1 = 1.f / l1;
    size_t r0g = rowbase + q0 + warp*16 + (lane >> 2);
    size_t cg  = colh + (lane & 3)*2;
#pragma unroll
    for (int nt = 0; nt < 16; nt++) {
        uint32_t hi0, lo0, hi1, lo1;
        split2(o[nt][0]*inv0, o[nt][1]*inv0, hi0, lo0);
        split2(o[nt][2]*inv1, o[nt][3]*inv1, hi1, lo1);
        size_t off0 = r0g*DIM + cg + nt*8;
        size_t off1 = (r0g+8)*DIM + cg + nt*8;
        *(uint32_t*)(Ohi + off0) = hi0;
        *(uint32_t*)(Olo + off0) = lo0;
        *(uint32_t*)(Ohi + off1) = hi1;
        *(uint32_t*)(Olo + off1) = lo1;
    }
}

// ============================================================
extern "C" void kernel_launch(void* const* d_in, const int* in_sizes, int n_in,
                              void* d_out, int out_size)
{
    const float* x   = (const float*)d_in[0];
    const float* wq  = (const float*)d_in[1];
    const float* wk  = (const float*)d_in[2];
    const float* wv  = (const float*)d_in[3];
    const float* wo  = (const float*)d_in[4];
    const float* fco = (const float*)d_in[5];
    const float* fsi = (const float*)d_in[6];
    float* out = (float*)d_out;

    float *Q, *K, *V;
    __nv_bfloat16 *Xhi, *Xlo, *Whi, *Wlo;
    __nv_bfloat16 *Qhi, *Qlo, *Khi, *Klo, *Vhi, *Vlo, *AThi, *ATlo;
    cudaGetSymbolAddress((void**)&Q, g_Q);
    cudaGetSymbolAddress((void**)&K, g_K);
    cudaGetSymbolAddress((void**)&V, g_V);
    cudaGetSymbolAddress((void**)&Xhi, g_Xhi);
    cudaGetSymbolAddress((void**)&Xlo, g_Xlo);
    cudaGetSymbolAddress((void**)&Whi, g_Whi);
    cudaGetSymbolAddress((void**)&Wlo, g_Wlo);
    cudaGetSymbolAddress((void**)&Qhi, g_Qhi);
    cudaGetSymbolAddress((void**)&Qlo, g_Qlo);
    cudaGetSymbolAddress((void**)&Khi, g_Khi);
    cudaGetSymbolAddress((void**)&Klo, g_Klo);
    cudaGetSymbolAddress((void**)&Vhi, g_Vhi);
    cudaGetSymbolAddress((void**)&Vlo, g_Vlo);
    cudaGetSymbolAddress((void**)&AThi, g_AThi);
    cudaGetSymbolAddress((void**)&ATlo, g_ATlo);

    cudaFuncSetAttribute(gemm_bf16x3,
        cudaFuncAttributeMaxDynamicSharedMemorySize, GEMM_SMEM);
    cudaFuncSetAttribute(attn_tc_kernel,
        cudaFuncAttributeMaxDynamicSharedMemorySize, ATTN_SMEM);

    const int nX4 = MROWS * DIM / 4;
    const int nW4 = DIM * DIM / 4;
    const size_t WSZ = (size_t)DIM * DIM;

    split_kernel<<<(nX4 + 255)/256, 256>>>(x,  Xhi, Xlo, nX4);
    split_kernel<<<(nW4 + 255)/256, 256>>>(wq, Whi + 0*WSZ, Wlo + 0*WSZ, nW4);
    split_kernel<<<(nW4 + 255)/256, 256>>>(wk, Whi + 1*WSZ, Wlo + 1*WSZ, nW4);
    split_kernel<<<(nW4 + 255)/256, 256>>>(wv, Whi + 2*WSZ, Wlo + 2*WSZ, nW4);
    split_kernel<<<(nW4 + 255)/256, 256>>>(wo, Whi + 3*WSZ, Wlo + 3*WSZ, nW4);

    dim3 ggrid(DIM / GBN, MROWS / GBM);
    gemm_bf16x3<<<ggrid, 256, GEMM_SMEM>>>(Xhi, Xlo, Whi + 0*WSZ, Wlo + 0*WSZ, Q, MROWS, DIM, DIM);
    gemm_bf16x3<<<ggrid, 256, GEMM_SMEM>>>(Xhi, Xlo, Whi + 1*WSZ, Wlo + 1*WSZ, K, MROWS, DIM, DIM);
    gemm_bf16x3<<<ggrid, 256, GEMM_SMEM>>>(Xhi, Xlo, Whi + 2*WSZ, Wlo + 2*WSZ, V, MROWS, DIM, DIM);

    int npairs = MROWS * NH * (HD / 2);
    rope_split_kernel<<<(npairs + 255)/256, 256>>>(Q, K, fco, fsi, Qhi, Qlo, Khi, Klo);
    split_kernel<<<(nX4 + 255)/256, 256>>>(V, Vhi, Vlo, nX4);

    dim3 agrid(SEQ / AQ, NH, BATCH);   // (32, 16, 2)
    attn_tc_kernel<<<agrid, 128, ATTN_SMEM>>>(Qhi, Qlo, Khi, Klo, Vhi, Vlo, AThi, ATlo);

    gemm_bf16x3<<<ggrid, 256, GEMM_SMEM>>>(AThi, ATlo, Whi + 3*WSZ, Wlo + 3*WSZ, out, MROWS, DIM, DIM);
}

// round 5
// speedup vs baseline: 4.3861x; 1.1120x over previous
#include <cuda_runtime.h>
#include <cuda_bf16.h>
#include <math.h>
#include <stdint.h>

#define DIM   2048
#define NH    16
#define HD    128
#define SEQ   2048
#define BATCH 2
#define MROWS (BATCH*SEQ)   // 4096
#define WSZ   ((size_t)DIM*DIM)

// ---- scratch (device globals) ----
__device__ __nv_bfloat16 g_Xhi[(size_t)MROWS*DIM];
__device__ __nv_bfloat16 g_Xlo[(size_t)MROWS*DIM];
__device__ __nv_bfloat16 g_Whi[4][WSZ];   // [K,N] layout
__device__ __nv_bfloat16 g_Wlo[4][WSZ];
__device__ __nv_bfloat16 g_Qhi[(size_t)MROWS*DIM];
__device__ __nv_bfloat16 g_Qlo[(size_t)MROWS*DIM];
__device__ __nv_bfloat16 g_Khi[(size_t)MROWS*DIM];
__device__ __nv_bfloat16 g_Klo[(size_t)MROWS*DIM];
__device__ __nv_bfloat16 g_Vhi[(size_t)MROWS*DIM];
__device__ __nv_bfloat16 g_Vlo[(size_t)MROWS*DIM];
__device__ __nv_bfloat16 g_AThi[(size_t)MROWS*DIM];
__device__ __nv_bfloat16 g_ATlo[(size_t)MROWS*DIM];

// ---------- PTX helpers ----------
__device__ __forceinline__ void cp16(uint32_t dst, const void* src) {
    asm volatile("cp.async.cg.shared.global [%0], [%1], 16;\n" :: "r"(dst), "l"(src));
}
__device__ __forceinline__ void ldsm4(uint32_t* r, uint32_t a) {
    asm volatile("ldmatrix.sync.aligned.m8n8.x4.shared.b16 {%0,%1,%2,%3}, [%4];\n"
        : "=r"(r[0]), "=r"(r[1]), "=r"(r[2]), "=r"(r[3]) : "r"(a));
}
__device__ __forceinline__ void ldsm4t(uint32_t* r, uint32_t a) {
    asm volatile("ldmatrix.sync.aligned.m8n8.x4.trans.shared.b16 {%0,%1,%2,%3}, [%4];\n"
        : "=r"(r[0]), "=r"(r[1]), "=r"(r[2]), "=r"(r[3]) : "r"(a));
}
__device__ __forceinline__ void mma16816(float* c, const uint32_t* a, const uint32_t* b) {
    asm volatile("mma.sync.aligned.m16n8k16.row.col.f32.bf16.bf16.f32 "
        "{%0,%1,%2,%3}, {%4,%5,%6,%7}, {%8,%9}, {%0,%1,%2,%3};\n"
        : "+f"(c[0]), "+f"(c[1]), "+f"(c[2]), "+f"(c[3])
        : "r"(a[0]), "r"(a[1]), "r"(a[2]), "r"(a[3]), "r"(b[0]), "r"(b[1]));
}
__device__ __forceinline__ uint32_t packbf(float x, float y) {
    __nv_bfloat162 t(__float2bfloat16(x), __float2bfloat16(y));
    return *(uint32_t*)&t;
}
__device__ __forceinline__ void split2(float x, float y, uint32_t& hi, uint32_t& lo) {
    float hx = __bfloat162float(__float2bfloat16(x));
    float hy = __bfloat162float(__float2bfloat16(y));
    hi = packbf(hx, hy);
    lo = packbf(x - hx, y - hy);
}
__device__ __forceinline__ uint32_t smem_u32(const void* p) {
    return (uint32_t)__cvta_generic_to_shared(p);
}

// ============================================================
// fp32 -> bf16 hi/lo split (vectorized x4)
// ============================================================
__global__ __launch_bounds__(256) void split_kernel(
    const float* __restrict__ in, __nv_bfloat16* __restrict__ hi,
    __nv_bfloat16* __restrict__ lo, int n4)
{
    int i = blockIdx.x * 256 + threadIdx.x;
    if (i >= n4) return;
    float4 v = ((const float4*)in)[i];
    uint32_t h0, l0, h1, l1;
    split2(v.x, v.y, h0, l0);
    split2(v.z, v.w, h1, l1);
    ((uint32_t*)hi)[2*i]   = h0;
    ((uint32_t*)hi)[2*i+1] = h1;
    ((uint32_t*)lo)[2*i]   = l0;
    ((uint32_t*)lo)[2*i+1] = l1;
}

// ============================================================
// bf16x3 mma.sync GEMM, BK=64, 3-stage cp.async ring,
// fused epilogue: mode 0 = rope+scale+split (Q), 1 = rope+split (K),
//                 2 = split (V), 3 = fp32 store (out)
// ============================================================
#define GBM 128
#define GBN 128
#define GBK 64
#define APAD 72
#define BPAD 136
#define SAB (GBM*APAD*2)            // 18432 bytes per A matrix
#define SBB (GBK*BPAD*2)            // 17408 bytes per B matrix
#define STAGE (2*SAB + 2*SBB)       // 71680
#define GEMM_SMEM (3*STAGE)         // 215040
#define NCHUNK (DIM / GBK)          // 32

__global__ __launch_bounds__(256, 1) void gemm_bf16x3(
    const __nv_bfloat16* __restrict__ Ah, const __nv_bfloat16* __restrict__ Al,
    const __nv_bfloat16* __restrict__ Bh, const __nv_bfloat16* __restrict__ Bl,
    __nv_bfloat16* __restrict__ Qh, __nv_bfloat16* __restrict__ Ql,
    __nv_bfloat16* __restrict__ Kh, __nv_bfloat16* __restrict__ Kl,
    __nv_bfloat16* __restrict__ Vh, __nv_bfloat16* __restrict__ Vl,
    float* __restrict__ Cout,
    const float* __restrict__ fcos, const float* __restrict__ fsin,
    int fused)
{
    extern __shared__ char smraw[];
    const uint32_t sb = smem_u32(smraw);

    const int tid  = threadIdx.x;
    const int row0 = blockIdx.y * GBM;
    const int col0 = blockIdx.x * GBN;
    const int z    = blockIdx.z;
    const int warp = tid >> 5, lane = tid & 31;
    const int wm = warp >> 2, wn = warp & 3;   // 2x4 warps, warp tile 64x32

    const __nv_bfloat16* bhp = Bh + (size_t)z * WSZ;
    const __nv_bfloat16* blp = Bl + (size_t)z * WSZ;
    __nv_bfloat16* Oh = (z == 0) ? Qh : (z == 1) ? Kh : Vh;
    __nv_bfloat16* Ol = (z == 0) ? Ql : (z == 1) ? Kl : Vl;
    const int mode = fused ? z : 3;

    float acc[4][4][4];
#pragma unroll
    for (int i = 0; i < 4; i++)
#pragma unroll
        for (int j = 0; j < 4; j++)
#pragma unroll
            for (int r = 0; r < 4; r++) acc[i][j][r] = 0.f;

    auto load_chunk = [&](int chunk) {
        const uint32_t base = sb + (uint32_t)(chunk % 3) * STAGE;
        const int k0 = chunk * GBK;
        // A: 128 rows x 64 k, hi+lo
        for (int idx = tid; idx < 1024; idx += 256) {
            int r = idx >> 3, o = (idx & 7) * 8;
            uint32_t d = base + (uint32_t)(r * APAD + o) * 2;
            size_t g = (size_t)(row0 + r) * DIM + k0 + o;
            cp16(d,       Ah + g);
            cp16(d + SAB, Al + g);
        }
        // B: 64 k-rows x 128 n, hi+lo  (W stored [K,N])
        for (int idx = tid; idx < 1024; idx += 256) {
            int r = idx >> 4, o = (idx & 15) * 8;
            uint32_t d = base + 2*SAB + (uint32_t)(r * BPAD + o) * 2;
            size_t g = (size_t)(k0 + r) * DIM + col0 + o;
            cp16(d,       bhp + g);
            cp16(d + SBB, blp + g);
        }
    };

    load_chunk(0);
    asm volatile("cp.async.commit_group;\n");
    load_chunk(1);
    asm volatile("cp.async.commit_group;\n");

    const int arow  = (lane & 7) + ((lane >> 3) & 1) * 8;
    const int acol8 = (lane >> 4) * 8;
    const int brow8 = (lane & 7) + ((lane >> 3) & 1) * 8;
    const int bnc8  = (lane >> 4) * 8;

    for (int i = 0; i < NCHUNK; i++) {
        asm volatile("cp.async.wait_group 1;\n");   // chunk i resident
        __syncthreads();                             // all warps done with chunk i-1
        if (i + 2 < NCHUNK) load_chunk(i + 2);       // buffer (i+2)%3 == (i-1)%3, free
        asm volatile("cp.async.commit_group;\n");    // unconditional: keeps accounting exact

        const uint32_t base = sb + (uint32_t)(i % 3) * STAGE;
        const uint32_t bAh = base, bAl = base + SAB;
        const uint32_t bBh = base + 2*SAB, bBl = base + 2*SAB + SBB;

#pragma unroll
        for (int ks = 0; ks < 4; ks++) {
            uint32_t ah[4][4], al[4][4];
            const int acol = ks * 16 + acol8;
#pragma unroll
            for (int mt = 0; mt < 4; mt++) {
                int r = wm * 64 + mt * 16 + arow;
                ldsm4(ah[mt], bAh + (uint32_t)(r * APAD + acol) * 2);
                ldsm4(al[mt], bAl + (uint32_t)(r * APAD + acol) * 2);
            }
            uint32_t bh[4][2], bl[4][2];
            const int brow = ks * 16 + brow8;
#pragma unroll
            for (int hh = 0; hh < 2; hh++) {
                int nc = wn * 32 + hh * 16 + bnc8;
                uint32_t t4[4];
                ldsm4t(t4, bBh + (uint32_t)(brow * BPAD + nc) * 2);
                bh[hh*2][0] = t4[0]; bh[hh*2][1] = t4[1];
                bh[hh*2+1][0] = t4[2]; bh[hh*2+1][1] = t4[3];
                ldsm4t(t4, bBl + (uint32_t)(brow * BPAD + nc) * 2);
                bl[hh*2][0] = t4[0]; bl[hh*2][1] = t4[1];
                bl[hh*2+1][0] = t4[2]; bl[hh*2+1][1] = t4[3];
            }
#pragma unroll
            for (int mt = 0; mt < 4; mt++)
#pragma unroll
                for (int nt = 0; nt < 4; nt++) {
                    mma16816(acc[mt][nt], ah[mt], bh[nt]);
                    mma16816(acc[mt][nt], ah[mt], bl[nt]);
                    mma16816(acc[mt][nt], al[mt], bh[nt]);
                }
        }
    }

    // ---- fused epilogue ----
    const float qscale = 0.08838834764831845f;   // 1/sqrt(128)
#pragma unroll
    for (int mt = 0; mt < 4; mt++) {
#pragma unroll
        for (int nt = 0; nt < 4; nt++) {
            int r = row0 + wm * 64 + mt * 16 + (lane >> 2);
            int c = col0 + wn * 32 + nt * 8 + (lane & 3) * 2;
            float a0 = acc[mt][nt][0], a1 = acc[mt][nt][1];
            float a2 = acc[mt][nt][2], a3 = acc[mt][nt][3];
            if (mode == 3) {
                *(float2*)(Cout + (size_t)r * DIM + c)       = make_float2(a0, a1);
                *(float2*)(Cout + (size_t)(r + 8) * DIM + c) = make_float2(a2, a3);
            } else {
                if (mode < 2) {
                    int i2 = (c & (HD - 1)) >> 1;
                    int s0 = r & (SEQ - 1), s1 = (r + 8) & (SEQ - 1);
                    float c0 = fcos[s0 * (HD/2) + i2], n0 = fsin[s0 * (HD/2) + i2];
                    float c1 = fcos[s1 * (HD/2) + i2], n1 = fsin[s1 * (HD/2) + i2];
                    float t0 = a0 * c0 - a1 * n0, t1 = a0 * n0 + a1 * c0;
                    float t2 = a2 * c1 - a3 * n1, t3 = a2 * n1 + a3 * c1;
                    if (mode == 0) { t0 *= qscale; t1 *= qscale; t2 *= qscale; t3 *= qscale; }
                    a0 = t0; a1 = t1; a2 = t2; a3 = t3;
                }
                uint32_t h0, l0, h1, l1;
                split2(a0, a1, h0, l0);
                split2(a2, a3, h1, l1);
                size_t o0 = (size_t)r * DIM + c, o1 = (size_t)(r + 8) * DIM + c;
                *(uint32_t*)(Oh + o0) = h0; *(uint32_t*)(Ol + o0) = l0;
                *(uint32_t*)(Oh + o1) = h1; *(uint32_t*)(Ol + o1) = l1;
            }
        }
    }
}

// ============================================================
// Tensor-core causal flash attention (bf16x3), 64x64 tiles, mma.sync.
// ============================================================
#define AQ  64
#define APD 136
#define TILE_E (AQ*APD)
#define ATTN_SMEM (6*TILE_E*2)

__global__ __launch_bounds__(128) void attn_tc_kernel(
    const __nv_bfloat16* __restrict__ Qhi, const __nv_bfloat16* __restrict__ Qlo,
    const __nv_bfloat16* __restrict__ Khi, const __nv_bfloat16* __restrict__ Klo,
    const __nv_bfloat16* __restrict__ Vhi, const __nv_bfloat16* __restrict__ Vlo,
    __nv_bfloat16* __restrict__ Ohi, __nv_bfloat16* __restrict__ Olo)
{
    extern __shared__ __nv_bfloat16 sm[];
    __nv_bfloat16* sQh = sm;
    __nv_bfloat16* sQl = sQh + TILE_E;
    __nv_bfloat16* sKh = sQl + TILE_E;
    __nv_bfloat16* sKl = sKh + TILE_E;
    __nv_bfloat16* sVh = sKl + TILE_E;
    __nv_bfloat16* sVl = sVh + TILE_E;
    const uint32_t uQh = smem_u32(sQh);
    const uint32_t uQl = smem_u32(sQl);
    const uint32_t uKh = smem_u32(sKh);
    const uint32_t uKl = smem_u32(sKl);
    const uint32_t uVh = smem_u32(sVh);
    const uint32_t uVl = smem_u32(sVl);

    const int tid = threadIdx.x, warp = tid >> 5, lane = tid & 31;
    const int qt = (int)(gridDim.x - 1 - blockIdx.x);
    const int h = blockIdx.y, b = blockIdx.z;
    const int q0 = qt * AQ;
    const size_t rowbase = (size_t)b * SEQ;
    const size_t colh = (size_t)h * HD;

#define LOADTILE(dstu, src, r0) do {                                           \
    for (int c0_ = tid; c0_ < 1024; c0_ += 128) {                              \
        int r_ = c0_ >> 4, o_ = (c0_ & 15) * 8;                                \
        cp16((dstu) + (r_*APD + o_)*2,                                         \
             (src) + (rowbase + (r0) + r_)*DIM + colh + o_);                   \
    } } while (0)

    LOADTILE(uQh, Qhi, q0);
    LOADTILE(uQl, Qlo, q0);
    LOADTILE(uKh, Khi, 0);
    LOADTILE(uKl, Klo, 0);
    asm volatile("cp.async.commit_group;\n");

    float o[16][4];
#pragma unroll
    for (int nt = 0; nt < 16; nt++)
#pragma unroll
        for (int r = 0; r < 4; r++) o[nt][r] = 0.f;
    float m0 = -INFINITY, m1 = -INFINITY, l0 = 0.f, l1 = 0.f;

    const int nkv = qt + 1;
    const int arow = (lane & 7) + ((lane >> 3) & 1) * 8;
    const int acol8 = (lane >> 4) * 8;
    const int bro8 = (lane & 7) + ((lane >> 4) << 3);
    const int bco8 = ((lane >> 3) & 1) * 8;
    const int vro8 = (lane & 7) + ((lane >> 3) & 1) * 8;
    const int vco8 = (lane >> 4) * 8;

    for (int kt = 0; kt < nkv; kt++) {
        asm volatile("cp.async.wait_group 0;\n");
        __syncthreads();

        LOADTILE(uVh, Vhi, kt*AQ);
        LOADTILE(uVl, Vlo, kt*AQ);
        asm volatile("cp.async.commit_group;\n");

        float s[8][4];
#pragma unroll
        for (int t = 0; t < 8; t++)
#pragma unroll
            for (int r = 0; r < 4; r++) s[t][r] = 0.f;

#pragma unroll
        for (int ks = 0; ks < 8; ks++) {
            uint32_t qh4[4], ql4[4];
            uint32_t aoff = ((warp*16 + arow)*APD + ks*16 + acol8)*2;
            ldsm4(qh4, uQh + aoff);
            ldsm4(ql4, uQl + aoff);
#pragma unroll
            for (int bt = 0; bt < 4; bt++) {
                uint32_t kh4[4], kl4[4];
                uint32_t boff = ((bt*16 + bro8)*APD + ks*16 + bco8)*2;
                ldsm4(kh4, uKh + boff);
                ldsm4(kl4, uKl + boff);
                mma16816(s[2*bt],   qh4, kh4);
                mma16816(s[2*bt],   qh4, kl4);
                mma16816(s[2*bt],   ql4, kh4);
                mma16816(s[2*bt+1], qh4, kh4+2);
                mma16816(s[2*bt+1], qh4, kl4+2);
                mma16816(s[2*bt+1], ql4, kh4+2);
            }
        }

        if (kt == qt) {
            int rl0 = warp*16 + (lane >> 2);
            int cb = (lane & 3) * 2;
#pragma unroll
            for (int t = 0; t < 8; t++) {
                int c0 = t*8 + cb, c1 = c0 + 1;
                if (c0 > rl0)     s[t][0] = -INFINITY;
                if (c1 > rl0)     s[t][1] = -INFINITY;
                if (c0 > rl0 + 8) s[t][2] = -INFINITY;
                if (c1 > rl0 + 8) s[t][3] = -INFINITY;
            }
        }

        float mt0 = -INFINITY, mt1 = -INFINITY;
#pragma unroll
        for (int t = 0; t < 8; t++) {
            mt0 = fmaxf(mt0, fmaxf(s[t][0], s[t][1]));
            mt1 = fmaxf(mt1, fmaxf(s[t][2], s[t][3]));
        }
        mt0 = fmaxf(mt0, __shfl_xor_sync(0xffffffffu, mt0, 1));
        mt0 = fmaxf(mt0, __shfl_xor_sync(0xffffffffu, mt0, 2));
        mt1 = fmaxf(mt1, __shfl_xor_sync(0xffffffffu, mt1, 1));
        mt1 = fmaxf(mt1, __shfl_xor_sync(0xffffffffu, mt1, 2));
        float mn0 = fmaxf(m0, mt0), mn1 = fmaxf(m1, mt1);
        float corr0 = __expf(m0 - mn0), corr1 = __expf(m1 - mn1);
        m0 = mn0; m1 = mn1;

        float p[8][4];
        float sum0 = 0.f, sum1 = 0.f;
#pragma unroll
        for (int t = 0; t < 8; t++) {
            p[t][0] = __expf(s[t][0] - mn0);
            p[t][1] = __expf(s[t][1] - mn0);
            p[t][2] = __expf(s[t][2] - mn1);
            p[t][3] = __expf(s[t][3] - mn1);
            sum0 += p[t][0] + p[t][1];
            sum1 += p[t][2] + p[t][3];
        }
        sum0 += __shfl_xor_sync(0xffffffffu, sum0, 1);
        sum0 += __shfl_xor_sync(0xffffffffu, sum0, 2);
        sum1 += __shfl_xor_sync(0xffffffffu, sum1, 1);
        sum1 += __shfl_xor_sync(0xffffffffu, sum1, 2);
        l0 = l0 * corr0 + sum0;
        l1 = l1 * corr1 + sum1;

        uint32_t ph[4][4], pl[4][4];
#pragma unroll
        for (int c = 0; c < 4; c++) {
            split2(p[2*c][0],   p[2*c][1],   ph[c][0], pl[c][0]);
            split2(p[2*c][2],   p[2*c][3],   ph[c][1], pl[c][1]);
            split2(p[2*c+1][0], p[2*c+1][1], ph[c][2], pl[c][2]);
            split2(p[2*c+1][2], p[2*c+1][3], ph[c][3], pl[c][3]);
        }

#pragma unroll
        for (int nt = 0; nt < 16; nt++) {
            o[nt][0] *= corr0; o[nt][1] *= corr0;
            o[nt][2] *= corr1; o[nt][3] *= corr1;
        }

        asm volatile("cp.async.wait_group 0;\n");
        __syncthreads();

        if (kt + 1 < nkv) {
            LOADTILE(uKh, Khi, (kt+1)*AQ);
            LOADTILE(uKl, Klo, (kt+1)*AQ);
        }
        asm volatile("cp.async.commit_group;\n");

#pragma unroll
        for (int c = 0; c < 4; c++) {
#pragma unroll
            for (int np = 0; np < 8; np++) {
                uint32_t vh4[4], vl4[4];
                uint32_t voff = ((c*16 + vro8)*APD + np*16 + vco8)*2;
                ldsm4t(vh4, uVh + voff);
                ldsm4t(vl4, uVl + voff);
                mma16816(o[2*np],   ph[c], vh4);
                mma16816(o[2*np],   ph[c], vl4);
                mma16816(o[2*np],   pl[c], vh4);
                mma16816(o[2*np+1], ph[c], vh4+2);
                mma16816(o[2*np+1], ph[c], vl4+2);
                mma16816(o[2*np+1], pl[c], vh4+2);
            }
        }
    }

    float inv0 = 1.f / l0, inv1 = 1.f / l1;
    size_t r0g = rowbase + q0 + warp*16 + (lane >> 2);
    size_t cg  = colh + (lane & 3)*2;
#pragma unroll
    for (int nt = 0; nt < 16; nt++) {
        uint32_t hi0, lo0, hi1, lo1;
        split2(o[nt][0]*inv0, o[nt][1]*inv0, hi0, lo0);
        split2(o[nt][2]*inv1, o[nt][3]*inv1, hi1, lo1);
        size_t off0 = r0g*DIM + cg + nt*8;
        size_t off1 = (r0g+8)*DIM + cg + nt*8;
        *(uint32_t*)(Ohi + off0) = hi0;
        *(uint32_t*)(Olo + off0) = lo0;
        *(uint32_t*)(Ohi + off1) = hi1;
        *(uint32_t*)(Olo + off1) = lo1;
    }
}

// ============================================================
extern "C" void kernel_launch(void* const* d_in, const int* in_sizes, int n_in,
                              void* d_out, int out_size)
{
    const float* x   = (const float*)d_in[0];
    const float* wq  = (const float*)d_in[1];
    const float* wk  = (const float*)d_in[2];
    const float* wv  = (const float*)d_in[3];
    const float* wo  = (const float*)d_in[4];
    const float* fco = (const float*)d_in[5];
    const float* fsi = (const float*)d_in[6];
    float* out = (float*)d_out;

    __nv_bfloat16 *Xhi, *Xlo, *Whi, *Wlo;
    __nv_bfloat16 *Qhi, *Qlo, *Khi, *Klo, *Vhi, *Vlo, *AThi, *ATlo;
    cudaGetSymbolAddress((void**)&Xhi, g_Xhi);
    cudaGetSymbolAddress((void**)&Xlo, g_Xlo);
    cudaGetSymbolAddress((void**)&Whi, g_Whi);
    cudaGetSymbolAddress((void**)&Wlo, g_Wlo);
    cudaGetSymbolAddress((void**)&Qhi, g_Qhi);
    cudaGetSymbolAddress((void**)&Qlo, g_Qlo);
    cudaGetSymbolAddress((void**)&Khi, g_Khi);
    cudaGetSymbolAddress((void**)&Klo, g_Klo);
    cudaGetSymbolAddress((void**)&Vhi, g_Vhi);
    cudaGetSymbolAddress((void**)&Vlo, g_Vlo);
    cudaGetSymbolAddress((void**)&AThi, g_AThi);
    cudaGetSymbolAddress((void**)&ATlo, g_ATlo);

    cudaFuncSetAttribute(gemm_bf16x3,
        cudaFuncAttributeMaxDynamicSharedMemorySize, GEMM_SMEM);
    cudaFuncSetAttribute(attn_tc_kernel,
        cudaFuncAttributeMaxDynamicSharedMemorySize, ATTN_SMEM);

    const int nX4 = MROWS * DIM / 4;
    const int nW4 = DIM * DIM / 4;

    split_kernel<<<(nX4 + 255)/256, 256>>>(x,  Xhi, Xlo, nX4);
    split_kernel<<<(nW4 + 255)/256, 256>>>(wq, Whi + 0*WSZ, Wlo + 0*WSZ, nW4);
    split_kernel<<<(nW4 + 255)/256, 256>>>(wk, Whi + 1*WSZ, Wlo + 1*WSZ, nW4);
    split_kernel<<<(nW4 + 255)/256, 256>>>(wv, Whi + 2*WSZ, Wlo + 2*WSZ, nW4);
    split_kernel<<<(nW4 + 255)/256, 256>>>(wo, Whi + 3*WSZ, Wlo + 3*WSZ, nW4);

    // fused QKV projection + rope + split epilogue
    dim3 qkvgrid(DIM/GBN, MROWS/GBM, 3);   // (16, 32, 3)
    gemm_bf16x3<<<qkvgrid, 256, GEMM_SMEM>>>(
        Xhi, Xlo, Whi, Wlo,
        Qhi, Qlo, Khi, Klo, Vhi, Vlo,
        nullptr, fco, fsi, 1);

    dim3 agrid(SEQ / AQ, NH, BATCH);       // (32, 16, 2)
    attn_tc_kernel<<<agrid, 128, ATTN_SMEM>>>(Qhi, Qlo, Khi, Klo, Vhi, Vlo, AThi, ATlo);

    // output projection (mode 3: fp32 store)
    dim3 ogrid(DIM/GBN, MROWS/GBM, 1);
    gemm_bf16x3<<<ogrid, 256, GEMM_SMEM>>>(
        AThi, ATlo, Whi + 3*WSZ, Wlo + 3*WSZ,
        nullptr, nullptr, nullptr, nullptr, nullptr, nullptr,
        out, fco, fsi, 0);
}

// round 6
// speedup vs baseline: 6.2311x; 1.4206x over previous
#include <cuda_runtime.h>
#include <cuda_fp16.h>
#include <math.h>
#include <stdint.h>

#define DIM   2048
#define NH    16
#define HD    128
#define SEQ   2048
#define BATCH 2
#define MROWS (BATCH*SEQ)   // 4096
#define WSZ   ((size_t)DIM*DIM)

// ---- scratch (device globals, all fp16) ----
__device__ __half g_Xhi[(size_t)MROWS*DIM];
__device__ __half g_Xlo[(size_t)MROWS*DIM];
__device__ __half g_W[4][WSZ];            // plain fp16, [K,N]
__device__ __half g_Qhi[(size_t)MROWS*DIM];
__device__ __half g_Qlo[(size_t)MROWS*DIM];
__device__ __half g_Kh [(size_t)MROWS*DIM];
__device__ __half g_Vh [(size_t)MROWS*DIM];
__device__ __half g_Ohi[(size_t)MROWS*DIM];
__device__ __half g_Olo[(size_t)MROWS*DIM];

// ---------- PTX helpers ----------
__device__ __forceinline__ void cp16(uint32_t dst, const void* src) {
    asm volatile("cp.async.cg.shared.global [%0], [%1], 16;\n" :: "r"(dst), "l"(src));
}
__device__ __forceinline__ void ldsm4(uint32_t* r, uint32_t a) {
    asm volatile("ldmatrix.sync.aligned.m8n8.x4.shared.b16 {%0,%1,%2,%3}, [%4];\n"
        : "=r"(r[0]), "=r"(r[1]), "=r"(r[2]), "=r"(r[3]) : "r"(a));
}
__device__ __forceinline__ void ldsm4t(uint32_t* r, uint32_t a) {
    asm volatile("ldmatrix.sync.aligned.m8n8.x4.trans.shared.b16 {%0,%1,%2,%3}, [%4];\n"
        : "=r"(r[0]), "=r"(r[1]), "=r"(r[2]), "=r"(r[3]) : "r"(a));
}
__device__ __forceinline__ void mma16816(float* c, const uint32_t* a, const uint32_t* b) {
    asm volatile("mma.sync.aligned.m16n8k16.row.col.f32.f16.f16.f32 "
        "{%0,%1,%2,%3}, {%4,%5,%6,%7}, {%8,%9}, {%0,%1,%2,%3};\n"
        : "+f"(c[0]), "+f"(c[1]), "+f"(c[2]), "+f"(c[3])
        : "r"(a[0]), "r"(a[1]), "r"(a[2]), "r"(a[3]), "r"(b[0]), "r"(b[1]));
}
__device__ __forceinline__ uint32_t packh(float x, float y) {
    __half2 t = __floats2half2_rn(x, y);
    return *(uint32_t*)&t;
}
__device__ __forceinline__ void split2h(float x, float y, uint32_t& hi, uint32_t& lo) {
    float hx = __half2float(__float2half_rn(x));
    float hy = __half2float(__float2half_rn(y));
    hi = packh(hx, hy);
    lo = packh(x - hx, y - hy);
}
__device__ __forceinline__ uint32_t smem_u32(const void* p) {
    return (uint32_t)__cvta_generic_to_shared(p);
}

// ============================================================
// fp32 -> fp16 hi/lo split (x4)
// ============================================================
__global__ __launch_bounds__(256) void split_kernel(
    const float* __restrict__ in, __half* __restrict__ hi,
    __half* __restrict__ lo, int n4)
{
    int i = blockIdx.x * 256 + threadIdx.x;
    if (i >= n4) return;
    float4 v = ((const float4*)in)[i];
    uint32_t h0, l0, h1, l1;
    split2h(v.x, v.y, h0, l0);
    split2h(v.z, v.w, h1, l1);
    ((uint32_t*)hi)[2*i]   = h0;
    ((uint32_t*)hi)[2*i+1] = h1;
    ((uint32_t*)lo)[2*i]   = l0;
    ((uint32_t*)lo)[2*i+1] = l1;
}

// fp32 -> fp16 convert (x4), no lo
__global__ __launch_bounds__(256) void cvt_kernel(
    const float* __restrict__ in, __half* __restrict__ out, int n4)
{
    int i = blockIdx.x * 256 + threadIdx.x;
    if (i >= n4) return;
    float4 v = ((const float4*)in)[i];
    ((uint32_t*)out)[2*i]   = packh(v.x, v.y);
    ((uint32_t*)out)[2*i+1] = packh(v.z, v.w);
}

// ============================================================
// fp16x2 mma.sync GEMM: C = (Ah+Al) @ B, BK=64, 3-stage ring.
// fused epilogue: mode 0 = rope+scale+split (Q), 1 = rope fp16 (K),
//                 2 = fp16 (V), 3 = fp32 store (out)
// ============================================================
#define GBM 128
#define GBN 128
#define GBK 64
#define APAD 72
#define BPAD 136
#define SAB (GBM*APAD*2)            // 18432 bytes per A matrix
#define SBB (GBK*BPAD*2)            // 17408 bytes (B single)
#define STAGE (2*SAB + SBB)         // 54272
#define GEMM_SMEM (3*STAGE)         // 162816
#define NCHUNK (DIM / GBK)          // 32

__global__ __launch_bounds__(256, 1) void gemm_fp16x2(
    const __half* __restrict__ Ah, const __half* __restrict__ Al,
    const __half* __restrict__ B,
    __half* __restrict__ Qh, __half* __restrict__ Ql,
    __half* __restrict__ Kh, __half* __restrict__ Vh,
    float* __restrict__ Cout,
    const float* __restrict__ fcos, const float* __restrict__ fsin,
    int fused)
{
    extern __shared__ char smraw[];
    const uint32_t sb = smem_u32(smraw);

    const int tid  = threadIdx.x;
    const int row0 = blockIdx.y * GBM;
    const int col0 = blockIdx.x * GBN;
    const int z    = blockIdx.z;
    const int warp = tid >> 5, lane = tid & 31;
    const int wm = warp >> 2, wn = warp & 3;   // 2x4 warps, warp tile 64x32

    const __half* bp = B + (size_t)z * WSZ;
    const int mode = fused ? z : 3;

    float acc[4][4][4];
#pragma unroll
    for (int i = 0; i < 4; i++)
#pragma unroll
        for (int j = 0; j < 4; j++)
#pragma unroll
            for (int r = 0; r < 4; r++) acc[i][j][r] = 0.f;

    auto load_chunk = [&](int chunk) {
        const uint32_t base = sb + (uint32_t)(chunk % 3) * STAGE;
        const int k0 = chunk * GBK;
        // A hi+lo: 128 rows x 64 k
        for (int idx = tid; idx < 1024; idx += 256) {
            int r = idx >> 3, o = (idx & 7) * 8;
            uint32_t d = base + (uint32_t)(r * APAD + o) * 2;
            size_t g = (size_t)(row0 + r) * DIM + k0 + o;
            cp16(d,       Ah + g);
            cp16(d + SAB, Al + g);
        }
        // B: 64 k-rows x 128 n
        for (int idx = tid; idx < 1024; idx += 256) {
            int r = idx >> 4, o = (idx & 15) * 8;
            uint32_t d = base + 2*SAB + (uint32_t)(r * BPAD + o) * 2;
            cp16(d, bp + (size_t)(k0 + r) * DIM + col0 + o);
        }
    };

    load_chunk(0);
    asm volatile("cp.async.commit_group;\n");
    load_chunk(1);
    asm volatile("cp.async.commit_group;\n");

    const int arow  = (lane & 7) + ((lane >> 3) & 1) * 8;
    const int acol8 = (lane >> 4) * 8;
    const int brow8 = (lane & 7) + ((lane >> 3) & 1) * 8;
    const int bnc8  = (lane >> 4) * 8;

    for (int i = 0; i < NCHUNK; i++) {
        asm volatile("cp.async.wait_group 1;\n");
        __syncthreads();
        if (i + 2 < NCHUNK) load_chunk(i + 2);
        asm volatile("cp.async.commit_group;\n");

        const uint32_t base = sb + (uint32_t)(i % 3) * STAGE;
        const uint32_t bAh = base, bAl = base + SAB;
        const uint32_t bB  = base + 2*SAB;

#pragma unroll
        for (int ks = 0; ks < 4; ks++) {
            uint32_t ah[4][4], al[4][4];
            const int acol = ks * 16 + acol8;
#pragma unroll
            for (int mt = 0; mt < 4; mt++) {
                int r = wm * 64 + mt * 16 + arow;
                ldsm4(ah[mt], bAh + (uint32_t)(r * APAD + acol) * 2);
                ldsm4(al[mt], bAl + (uint32_t)(r * APAD + acol) * 2);
            }
            uint32_t bfr[4][2];
            const int brow = ks * 16 + brow8;
#pragma unroll
            for (int hh = 0; hh < 2; hh++) {
                int nc = wn * 32 + hh * 16 + bnc8;
                uint32_t t4[4];
                ldsm4t(t4, bB + (uint32_t)(brow * BPAD + nc) * 2);
                bfr[hh*2][0] = t4[0]; bfr[hh*2][1] = t4[1];
                bfr[hh*2+1][0] = t4[2]; bfr[hh*2+1][1] = t4[3];
            }
#pragma unroll
            for (int mt = 0; mt < 4; mt++)
#pragma unroll
                for (int nt = 0; nt < 4; nt++) {
                    mma16816(acc[mt][nt], ah[mt], bfr[nt]);
                    mma16816(acc[mt][nt], al[mt], bfr[nt]);
                }
        }
    }

    // ---- fused epilogue ----
    const float qscale = 0.08838834764831845f;   // 1/sqrt(128)
#pragma unroll
    for (int mt = 0; mt < 4; mt++) {
#pragma unroll
        for (int nt = 0; nt < 4; nt++) {
            int r = row0 + wm * 64 + mt * 16 + (lane >> 2);
            int c = col0 + wn * 32 + nt * 8 + (lane & 3) * 2;
            float a0 = acc[mt][nt][0], a1 = acc[mt][nt][1];
            float a2 = acc[mt][nt][2], a3 = acc[mt][nt][3];
            size_t o0 = (size_t)r * DIM + c, o1 = (size_t)(r + 8) * DIM + c;
            if (mode == 3) {
                *(float2*)(Cout + o0) = make_float2(a0, a1);
                *(float2*)(Cout + o1) = make_float2(a2, a3);
            } else if (mode == 2) {
                *(uint32_t*)(Vh + o0) = packh(a0, a1);
                *(uint32_t*)(Vh + o1) = packh(a2, a3);
            } else {
                int i2 = (c & (HD - 1)) >> 1;
                int s0 = r & (SEQ - 1), s1 = (r + 8) & (SEQ - 1);
                float c0 = fcos[s0 * (HD/2) + i2], n0 = fsin[s0 * (HD/2) + i2];
                float c1 = fcos[s1 * (HD/2) + i2], n1 = fsin[s1 * (HD/2) + i2];
                float t0 = a0 * c0 - a1 * n0, t1 = a0 * n0 + a1 * c0;
                float t2 = a2 * c1 - a3 * n1, t3 = a2 * n1 + a3 * c1;
                if (mode == 0) {
                    t0 *= qscale; t1 *= qscale; t2 *= qscale; t3 *= qscale;
                    uint32_t h0, l0, h1, l1;
                    split2h(t0, t1, h0, l0);
                    split2h(t2, t3, h1, l1);
                    *(uint32_t*)(Qh + o0) = h0; *(uint32_t*)(Ql + o0) = l0;
                    *(uint32_t*)(Qh + o1) = h1; *(uint32_t*)(Ql + o1) = l1;
                } else {
                    *(uint32_t*)(Kh + o0) = packh(t0, t1);
                    *(uint32_t*)(Kh + o1) = packh(t2, t3);
                }
            }
        }
    }
}

// ============================================================
// fp16x2 causal flash attention, 64x64 tiles, mma.sync.
// Q split hi/lo; K, V plain fp16. P split in registers.
// ============================================================
#define AQ  64
#define APD 136
#define TILE_E (AQ*APD)
#define ATTN_SMEM (4*TILE_E*2)     // Qh,Ql,K,V = 69632

__global__ __launch_bounds__(128) void attn_tc_kernel(
    const __half* __restrict__ Qhi, const __half* __restrict__ Qlo,
    const __half* __restrict__ Kg,  const __half* __restrict__ Vg,
    __half* __restrict__ Ohi, __half* __restrict__ Olo)
{
    extern __shared__ __half sm[];
    __half* sQh = sm;
    __half* sQl = sQh + TILE_E;
    __half* sK  = sQl + TILE_E;
    __half* sV  = sK  + TILE_E;
    const uint32_t uQh = smem_u32(sQh);
    const uint32_t uQl = smem_u32(sQl);
    const uint32_t uK  = smem_u32(sK);
    const uint32_t uV  = smem_u32(sV);

    const int tid = threadIdx.x, warp = tid >> 5, lane = tid & 31;
    const int qt = (int)(gridDim.x - 1 - blockIdx.x);   // heavy tiles first
    const int h = blockIdx.y, b = blockIdx.z;
    const int q0 = qt * AQ;
    const size_t rowbase = (size_t)b * SEQ;
    const size_t colh = (size_t)h * HD;

#define LOADTILE(dstu, src, r0) do {                                           \
    for (int c0_ = tid; c0_ < 1024; c0_ += 128) {                              \
        int r_ = c0_ >> 4, o_ = (c0_ & 15) * 8;                                \
        cp16((dstu) + (r_*APD + o_)*2,                                         \
             (src) + (rowbase + (r0) + r_)*DIM + colh + o_);                   \
    } } while (0)

    LOADTILE(uQh, Qhi, q0);
    LOADTILE(uQl, Qlo, q0);
    LOADTILE(uK,  Kg,  0);
    asm volatile("cp.async.commit_group;\n");

    float o[16][4];
#pragma unroll
    for (int nt = 0; nt < 16; nt++)
#pragma unroll
        for (int r = 0; r < 4; r++) o[nt][r] = 0.f;
    float m0 = -INFINITY, m1 = -INFINITY, l0 = 0.f, l1 = 0.f;

    const int nkv = qt + 1;
    const int arow = (lane & 7) + ((lane >> 3) & 1) * 8;
    const int acol8 = (lane >> 4) * 8;
    const int bro8 = (lane & 7) + ((lane >> 4) << 3);
    const int bco8 = ((lane >> 3) & 1) * 8;
    const int vro8 = (lane & 7) + ((lane >> 3) & 1) * 8;
    const int vco8 = (lane >> 4) * 8;

    for (int kt = 0; kt < nkv; kt++) {
        asm volatile("cp.async.wait_group 0;\n");
        __syncthreads();

        LOADTILE(uV, Vg, kt*AQ);
        asm volatile("cp.async.commit_group;\n");

        // ---- S = (Qh+Ql) K^T ----
        float s[8][4];
#pragma unroll
        for (int t = 0; t < 8; t++)
#pragma unroll
            for (int r = 0; r < 4; r++) s[t][r] = 0.f;

#pragma unroll
        for (int ks = 0; ks < 8; ks++) {
            uint32_t qh4[4], ql4[4];
            uint32_t aoff = ((warp*16 + arow)*APD + ks*16 + acol8)*2;
            ldsm4(qh4, uQh + aoff);
            ldsm4(ql4, uQl + aoff);
#pragma unroll
            for (int bt = 0; bt < 4; bt++) {
                uint32_t kh4[4];
                uint32_t boff = ((bt*16 + bro8)*APD + ks*16 + bco8)*2;
                ldsm4(kh4, uK + boff);
                mma16816(s[2*bt],   qh4, kh4);
                mma16816(s[2*bt],   ql4, kh4);
                mma16816(s[2*bt+1], qh4, kh4+2);
                mma16816(s[2*bt+1], ql4, kh4+2);
            }
        }

        // ---- causal mask on diagonal tile ----
        if (kt == qt) {
            int rl0 = warp*16 + (lane >> 2);
            int cb = (lane & 3) * 2;
#pragma unroll
            for (int t = 0; t < 8; t++) {
                int c0 = t*8 + cb, c1 = c0 + 1;
                if (c0 > rl0)     s[t][0] = -INFINITY;
                if (c1 > rl0)     s[t][1] = -INFINITY;
                if (c0 > rl0 + 8) s[t][2] = -INFINITY;
                if (c1 > rl0 + 8) s[t][3] = -INFINITY;
            }
        }

        // ---- online softmax ----
        float mt0 = -INFINITY, mt1 = -INFINITY;
#pragma unroll
        for (int t = 0; t < 8; t++) {
            mt0 = fmaxf(mt0, fmaxf(s[t][0], s[t][1]));
            mt1 = fmaxf(mt1, fmaxf(s[t][2], s[t][3]));
        }
        mt0 = fmaxf(mt0, __shfl_xor_sync(0xffffffffu, mt0, 1));
        mt0 = fmaxf(mt0, __shfl_xor_sync(0xffffffffu, mt0, 2));
        mt1 = fmaxf(mt1, __shfl_xor_sync(0xffffffffu, mt1, 1));
        mt1 = fmaxf(mt1, __shfl_xor_sync(0xffffffffu, mt1, 2));
        float mn0 = fmaxf(m0, mt0), mn1 = fmaxf(m1, mt1);
        float corr0 = __expf(m0 - mn0), corr1 = __expf(m1 - mn1);
        m0 = mn0; m1 = mn1;

        float p[8][4];
        float sum0 = 0.f, sum1 = 0.f;
#pragma unroll
        for (int t = 0; t < 8; t++) {
            p[t][0] = __expf(s[t][0] - mn0);
            p[t][1] = __expf(s[t][1] - mn0);
            p[t][2] = __expf(s[t][2] - mn1);
            p[t][3] = __expf(s[t][3] - mn1);
            sum0 += p[t][0] + p[t][1];
            sum1 += p[t][2] + p[t][3];
        }
        sum0 += __shfl_xor_sync(0xffffffffu, sum0, 1);
        sum0 += __shfl_xor_sync(0xffffffffu, sum0, 2);
        sum1 += __shfl_xor_sync(0xffffffffu, sum1, 1);
        sum1 += __shfl_xor_sync(0xffffffffu, sum1, 2);
        l0 = l0 * corr0 + sum0;
        l1 = l1 * corr1 + sum1;

        // split P -> hi/lo A-fragments
        uint32_t ph[4][4], pl[4][4];
#pragma unroll
        for (int c = 0; c < 4; c++) {
            split2h(p[2*c][0],   p[2*c][1],   ph[c][0], pl[c][0]);
            split2h(p[2*c][2],   p[2*c][3],   ph[c][1], pl[c][1]);
            split2h(p[2*c+1][0], p[2*c+1][1], ph[c][2], pl[c][2]);
            split2h(p[2*c+1][2], p[2*c+1][3], ph[c][3], pl[c][3]);
        }

#pragma unroll
        for (int nt = 0; nt < 16; nt++) {
            o[nt][0] *= corr0; o[nt][1] *= corr0;
            o[nt][2] *= corr1; o[nt][3] *= corr1;
        }

        asm volatile("cp.async.wait_group 0;\n");   // V ready
        __syncthreads();

        if (kt + 1 < nkv) {
            LOADTILE(uK, Kg, (kt+1)*AQ);
        }
        asm volatile("cp.async.commit_group;\n");

        // ---- O += (Ph+Pl) V ----
#pragma unroll
        for (int c = 0; c < 4; c++) {
#pragma unroll
            for (int np = 0; np < 8; np++) {
                uint32_t vh4[4];
                uint32_t voff = ((c*16 + vro8)*APD + np*16 + vco8)*2;
                ldsm4t(vh4, uV + voff);
                mma16816(o[2*np],   ph[c], vh4);
                mma16816(o[2*np],   pl[c], vh4);
                mma16816(o[2*np+1], ph[c], vh4+2);
                mma16816(o[2*np+1], pl[c], vh4+2);
            }
        }
    }

    // ---- finalize ----
    float inv0 = 1.f / l0, inv1 = 1.f / l1;
    size_t r0g = rowbase + q0 + warp*16 + (lane >> 2);
    size_t cg  = colh + (lane & 3)*2;
#pragma unroll
    for (int nt = 0; nt < 16; nt++) {
        uint32_t hi0, lo0, hi1, lo1;
        split2h(o[nt][0]*inv0, o[nt][1]*inv0, hi0, lo0);
        split2h(o[nt][2]*inv1, o[nt][3]*inv1, hi1, lo1);
        size_t off0 = r0g*DIM + cg + nt*8;
        size_t off1 = (r0g+8)*DIM + cg + nt*8;
        *(uint32_t*)(Ohi + off0) = hi0;
        *(uint32_t*)(Olo + off0) = lo0;
        *(uint32_t*)(Ohi + off1) = hi1;
        *(uint32_t*)(Olo + off1) = lo1;
    }
}

// ============================================================
extern "C" void kernel_launch(void* const* d_in, const int* in_sizes, int n_in,
                              void* d_out, int out_size)
{
    const float* x   = (const float*)d_in[0];
    const float* wq  = (const float*)d_in[1];
    const float* wk  = (const float*)d_in[2];
    const float* wv  = (const float*)d_in[3];
    const float* wo  = (const float*)d_in[4];
    const float* fco = (const float*)d_in[5];
    const float* fsi = (const float*)d_in[6];
    float* out = (float*)d_out;

    __half *Xhi, *Xlo, *W, *Qhi, *Qlo, *Kh, *Vh, *Ohi, *Olo;
    cudaGetSymbolAddress((void**)&Xhi, g_Xhi);
    cudaGetSymbolAddress((void**)&Xlo, g_Xlo);
    cudaGetSymbolAddress((void**)&W,   g_W);
    cudaGetSymbolAddress((void**)&Qhi, g_Qhi);
    cudaGetSymbolAddress((void**)&Qlo, g_Qlo);
    cudaGetSymbolAddress((void**)&Kh,  g_Kh);
    cudaGetSymbolAddress((void**)&Vh,  g_Vh);
    cudaGetSymbolAddress((void**)&Ohi, g_Ohi);
    cudaGetSymbolAddress((void**)&Olo, g_Olo);

    cudaFuncSetAttribute(gemm_fp16x2,
        cudaFuncAttributeMaxDynamicSharedMemorySize, GEMM_SMEM);
    cudaFuncSetAttribute(attn_tc_kernel,
        cudaFuncAttributeMaxDynamicSharedMemorySize, ATTN_SMEM);

    const int nX4 = MROWS * DIM / 4;
    const int nW4 = DIM * DIM / 4;

    split_kernel<<<(nX4 + 255)/256, 256>>>(x, Xhi, Xlo, nX4);
    cvt_kernel<<<(nW4 + 255)/256, 256>>>(wq, W + 0*WSZ, nW4);
    cvt_kernel<<<(nW4 + 255)/256, 256>>>(wk, W + 1*WSZ, nW4);
    cvt_kernel<<<(nW4 + 255)/256, 256>>>(wv, W + 2*WSZ, nW4);
    cvt_kernel<<<(nW4 + 255)/256, 256>>>(wo, W + 3*WSZ, nW4);

    // fused QKV projection + rope + split epilogue
    dim3 qkvgrid(DIM/GBN, MROWS/GBM, 3);   // (16, 32, 3)
    gemm_fp16x2<<<qkvgrid, 256, GEMM_SMEM>>>(
        Xhi, Xlo, W,
        Qhi, Qlo, Kh, Vh,
        nullptr, fco, fsi, 1);

    dim3 agrid(SEQ / AQ, NH, BATCH);       // (32, 16, 2)
    attn_tc_kernel<<<agrid, 128, ATTN_SMEM>>>(Qhi, Qlo, Kh, Vh, Ohi, Olo);

    // output projection (mode 3: fp32 store)
    dim3 ogrid(DIM/GBN, MROWS/GBM, 1);
    gemm_fp16x2<<<ogrid, 256, GEMM_SMEM>>>(
        Ohi, Olo, W + 3*WSZ,
        nullptr, nullptr, nullptr, nullptr,
        out, fco, fsi, 0);
}

// round 7
// speedup vs baseline: 6.3539x; 1.0197x over previous
#include <cuda_runtime.h>
#include <cuda_fp16.h>
#include <math.h>
#include <stdint.h>

#define DIM   2048
#define NH    16
#define HD    128
#define SEQ   2048
#define BATCH 2
#define MROWS (BATCH*SEQ)   // 4096
#define WSZ   ((size_t)DIM*DIM)

// ---- scratch (device globals, all fp16) ----
__device__ __half g_Xhi[(size_t)MROWS*DIM];
__device__ __half g_Xlo[(size_t)MROWS*DIM];
__device__ __half g_W[4][WSZ];            // plain fp16, [K,N]
__device__ __half g_Qhi[(size_t)MROWS*DIM];
__device__ __half g_Qlo[(size_t)MROWS*DIM];
__device__ __half g_Kh [(size_t)MROWS*DIM];
__device__ __half g_Vh [(size_t)MROWS*DIM];
__device__ __half g_Ohi[(size_t)MROWS*DIM];
__device__ __half g_Olo[(size_t)MROWS*DIM];

// ---------- PTX helpers ----------
__device__ __forceinline__ void cp16(uint32_t dst, const void* src) {
    asm volatile("cp.async.cg.shared.global [%0], [%1], 16;\n" :: "r"(dst), "l"(src));
}
__device__ __forceinline__ void ldsm4(uint32_t* r, uint32_t a) {
    asm volatile("ldmatrix.sync.aligned.m8n8.x4.shared.b16 {%0,%1,%2,%3}, [%4];\n"
        : "=r"(r[0]), "=r"(r[1]), "=r"(r[2]), "=r"(r[3]) : "r"(a));
}
__device__ __forceinline__ void ldsm4t(uint32_t* r, uint32_t a) {
    asm volatile("ldmatrix.sync.aligned.m8n8.x4.trans.shared.b16 {%0,%1,%2,%3}, [%4];\n"
        : "=r"(r[0]), "=r"(r[1]), "=r"(r[2]), "=r"(r[3]) : "r"(a));
}
__device__ __forceinline__ void mma16816(float* c, const uint32_t* a, const uint32_t* b) {
    asm volatile("mma.sync.aligned.m16n8k16.row.col.f32.f16.f16.f32 "
        "{%0,%1,%2,%3}, {%4,%5,%6,%7}, {%8,%9}, {%0,%1,%2,%3};\n"
        : "+f"(c[0]), "+f"(c[1]), "+f"(c[2]), "+f"(c[3])
        : "r"(a[0]), "r"(a[1]), "r"(a[2]), "r"(a[3]), "r"(b[0]), "r"(b[1]));
}
__device__ __forceinline__ uint32_t packh(float x, float y) {
    __half2 t = __floats2half2_rn(x, y);
    return *(uint32_t*)&t;
}
__device__ __forceinline__ void split2h(float x, float y, uint32_t& hi, uint32_t& lo) {
    float hx = __half2float(__float2half_rn(x));
    float hy = __half2float(__float2half_rn(y));
    hi = packh(hx, hy);
    lo = packh(x - hx, y - hy);
}
__device__ __forceinline__ uint32_t smem_u32(const void* p) {
    return (uint32_t)__cvta_generic_to_shared(p);
}

// ============================================================
// fp32 -> fp16 hi/lo split (x4)
// ============================================================
__global__ __launch_bounds__(256) void split_kernel(
    const float* __restrict__ in, __half* __restrict__ hi,
    __half* __restrict__ lo, int n4)
{
    int i = blockIdx.x * 256 + threadIdx.x;
    if (i >= n4) return;
    float4 v = ((const float4*)in)[i];
    uint32_t h0, l0, h1, l1;
    split2h(v.x, v.y, h0, l0);
    split2h(v.z, v.w, h1, l1);
    ((uint32_t*)hi)[2*i]   = h0;
    ((uint32_t*)hi)[2*i+1] = h1;
    ((uint32_t*)lo)[2*i]   = l0;
    ((uint32_t*)lo)[2*i+1] = l1;
}

// fp32 -> fp16 convert of all 4 weights in one launch (z selects weight)
__global__ __launch_bounds__(256) void cvt4_kernel(
    const float* __restrict__ w0, const float* __restrict__ w1,
    const float* __restrict__ w2, const float* __restrict__ w3,
    __half* __restrict__ out, int n4)
{
    int i = blockIdx.x * 256 + threadIdx.x;
    if (i >= n4) return;
    int z = blockIdx.y;
    const float* in = (z == 0) ? w0 : (z == 1) ? w1 : (z == 2) ? w2 : w3;
    __half* o = out + (size_t)z * WSZ;
    float4 v = ((const float4*)in)[i];
    ((uint32_t*)o)[2*i]   = packh(v.x, v.y);
    ((uint32_t*)o)[2*i+1] = packh(v.z, v.w);
}

// ============================================================
// fp16x2 mma.sync GEMM: C = (Ah+Al) @ B, BK=64, 2-stage ring,
// 2 CTAs/SM for cross-CTA bubble hiding.
// fused epilogue: mode 0 = rope+scale+split (Q), 1 = rope fp16 (K),
//                 2 = fp16 (V), 3 = fp32 store (out)
// ============================================================
#define GBM 128
#define GBN 128
#define GBK 64
#define APAD 72
#define BPAD 136
#define SAB (GBM*APAD*2)            // 18432 bytes per A matrix
#define SBB (GBK*BPAD*2)            // 17408 bytes (B single)
#define STAGE (2*SAB + SBB)         // 54272
#define GEMM_SMEM (2*STAGE)         // 108544 -> 2 CTAs/SM
#define NCHUNK (DIM / GBK)          // 32

__global__ __launch_bounds__(256, 2) void gemm_fp16x2(
    const __half* __restrict__ Ah, const __half* __restrict__ Al,
    const __half* __restrict__ B,
    __half* __restrict__ Qh, __half* __restrict__ Ql,
    __half* __restrict__ Kh, __half* __restrict__ Vh,
    float* __restrict__ Cout,
    const float* __restrict__ fcos, const float* __restrict__ fsin,
    int fused)
{
    extern __shared__ char smraw[];
    const uint32_t sb = smem_u32(smraw);

    const int tid  = threadIdx.x;
    const int row0 = blockIdx.y * GBM;
    const int col0 = blockIdx.x * GBN;
    const int z    = blockIdx.z;
    const int warp = tid >> 5, lane = tid & 31;
    const int wm = warp >> 2, wn = warp & 3;   // 2x4 warps, warp tile 64x32

    const __half* bp = B + (size_t)z * WSZ;
    const int mode = fused ? z : 3;

    float acc[4][4][4];
#pragma unroll
    for (int i = 0; i < 4; i++)
#pragma unroll
        for (int j = 0; j < 4; j++)
#pragma unroll
            for (int r = 0; r < 4; r++) acc[i][j][r] = 0.f;

    auto load_chunk = [&](int chunk) {
        const uint32_t base = sb + (uint32_t)(chunk & 1) * STAGE;
        const int k0 = chunk * GBK;
        // A hi+lo: 128 rows x 64 k
        for (int idx = tid; idx < 1024; idx += 256) {
            int r = idx >> 3, o = (idx & 7) * 8;
            uint32_t d = base + (uint32_t)(r * APAD + o) * 2;
            size_t g = (size_t)(row0 + r) * DIM + k0 + o;
            cp16(d,       Ah + g);
            cp16(d + SAB, Al + g);
        }
        // B: 64 k-rows x 128 n
        for (int idx = tid; idx < 1024; idx += 256) {
            int r = idx >> 4, o = (idx & 15) * 8;
            uint32_t d = base + 2*SAB + (uint32_t)(r * BPAD + o) * 2;
            cp16(d, bp + (size_t)(k0 + r) * DIM + col0 + o);
        }
    };

    load_chunk(0);
    asm volatile("cp.async.commit_group;\n");
    load_chunk(1);
    asm volatile("cp.async.commit_group;\n");

    const int arow  = (lane & 7) + ((lane >> 3) & 1) * 8;
    const int acol8 = (lane >> 4) * 8;
    const int brow8 = (lane & 7) + ((lane >> 3) & 1) * 8;
    const int bnc8  = (lane >> 4) * 8;

    for (int i = 0; i < NCHUNK; i++) {
        asm volatile("cp.async.wait_group 1;\n");   // chunk i resident
        __syncthreads();

        const uint32_t base = sb + (uint32_t)(i & 1) * STAGE;
        const uint32_t bAh = base, bAl = base + SAB;
        const uint32_t bB  = base + 2*SAB;

#pragma unroll
        for (int ks = 0; ks < 4; ks++) {
            uint32_t ah[4][4], al[4][4];
            const int acol = ks * 16 + acol8;
#pragma unroll
            for (int mt = 0; mt < 4; mt++) {
                int r = wm * 64 + mt * 16 + arow;
                ldsm4(ah[mt], bAh + (uint32_t)(r * APAD + acol) * 2);
                ldsm4(al[mt], bAl + (uint32_t)(r * APAD + acol) * 2);
            }
            uint32_t bfr[4][2];
            const int brow = ks * 16 + brow8;
#pragma unroll
            for (int hh = 0; hh < 2; hh++) {
                int nc = wn * 32 + hh * 16 + bnc8;
                uint32_t t4[4];
                ldsm4t(t4, bB + (uint32_t)(brow * BPAD + nc) * 2);
                bfr[hh*2][0] = t4[0]; bfr[hh*2][1] = t4[1];
                bfr[hh*2+1][0] = t4[2]; bfr[hh*2+1][1] = t4[3];
            }
#pragma unroll
            for (int mt = 0; mt < 4; mt++)
#pragma unroll
                for (int nt = 0; nt < 4; nt++) {
                    mma16816(acc[mt][nt], ah[mt], bfr[nt]);
                    mma16816(acc[mt][nt], al[mt], bfr[nt]);
                }
        }

        __syncthreads();                             // all readers of buf i&1 done
        if (i + 2 < NCHUNK) load_chunk(i + 2);
        asm volatile("cp.async.commit_group;\n");    // one group per iter, exact accounting
    }

    // ---- fused epilogue ----
    const float qscale = 0.08838834764831845f;   // 1/sqrt(128)
#pragma unroll
    for (int mt = 0; mt < 4; mt++) {
#pragma unroll
        for (int nt = 0; nt < 4; nt++) {
            int r = row0 + wm * 64 + mt * 16 + (lane >> 2);
            int c = col0 + wn * 32 + nt * 8 + (lane & 3) * 2;
            float a0 = acc[mt][nt][0], a1 = acc[mt][nt][1];
            float a2 = acc[mt][nt][2], a3 = acc[mt][nt][3];
            size_t o0 = (size_t)r * DIM + c, o1 = (size_t)(r + 8) * DIM + c;
            if (mode == 3) {
                *(float2*)(Cout + o0) = make_float2(a0, a1);
                *(float2*)(Cout + o1) = make_float2(a2, a3);
            } else if (mode == 2) {
                *(uint32_t*)(Vh + o0) = packh(a0, a1);
                *(uint32_t*)(Vh + o1) = packh(a2, a3);
            } else {
                int i2 = (c & (HD - 1)) >> 1;
                int s0 = r & (SEQ - 1), s1 = (r + 8) & (SEQ - 1);
                float c0 = fcos[s0 * (HD/2) + i2], n0 = fsin[s0 * (HD/2) + i2];
                float c1 = fcos[s1 * (HD/2) + i2], n1 = fsin[s1 * (HD/2) + i2];
                float t0 = a0 * c0 - a1 * n0, t1 = a0 * n0 + a1 * c0;
                float t2 = a2 * c1 - a3 * n1, t3 = a2 * n1 + a3 * c1;
                if (mode == 0) {
                    t0 *= qscale; t1 *= qscale; t2 *= qscale; t3 *= qscale;
                    uint32_t h0, l0, h1, l1;
                    split2h(t0, t1, h0, l0);
                    split2h(t2, t3, h1, l1);
                    *(uint32_t*)(Qh + o0) = h0; *(uint32_t*)(Ql + o0) = l0;
                    *(uint32_t*)(Qh + o1) = h1; *(uint32_t*)(Ql + o1) = l1;
                } else {
                    *(uint32_t*)(Kh + o0) = packh(t0, t1);
                    *(uint32_t*)(Kh + o1) = packh(t2, t3);
                }
            }
        }
    }
}

// ============================================================
// fp16x2 causal flash attention, 64x64 tiles, mma.sync.
// Q split hi/lo; K, V plain fp16. P split in registers.
// ============================================================
#define AQ  64
#define APD 136
#define TILE_E (AQ*APD)
#define ATTN_SMEM (4*TILE_E*2)     // Qh,Ql,K,V = 69632 -> 3 CTAs/SM

__global__ __launch_bounds__(128) void attn_tc_kernel(
    const __half* __restrict__ Qhi, const __half* __restrict__ Qlo,
    const __half* __restrict__ Kg,  const __half* __restrict__ Vg,
    __half* __restrict__ Ohi, __half* __restrict__ Olo)
{
    extern __shared__ __half sm[];
    __half* sQh = sm;
    __half* sQl = sQh + TILE_E;
    __half* sK  = sQl + TILE_E;
    __half* sV  = sK  + TILE_E;
    const uint32_t uQh = smem_u32(sQh);
    const uint32_t uQl = smem_u32(sQl);
    const uint32_t uK  = smem_u32(sK);
    const uint32_t uV  = smem_u32(sV);

    const int tid = threadIdx.x, warp = tid >> 5, lane = tid & 31;
    const int qt = (int)(gridDim.x - 1 - blockIdx.x);   // heavy tiles first
    const int h = blockIdx.y, b = blockIdx.z;
    const int q0 = qt * AQ;
    const size_t rowbase = (size_t)b * SEQ;
    const size_t colh = (size_t)h * HD;

#define LOADTILE(dstu, src, r0) do {                                           \
    for (int c0_ = tid; c0_ < 1024; c0_ += 128) {                              \
        int r_ = c0_ >> 4, o_ = (c0_ & 15) * 8;                                \
        cp16((dstu) + (r_*APD + o_)*2,                                         \
             (src) + (rowbase + (r0) + r_)*DIM + colh + o_);                   \
    } } while (0)

    LOADTILE(uQh, Qhi, q0);
    LOADTILE(uQl, Qlo, q0);
    LOADTILE(uK,  Kg,  0);
    asm volatile("cp.async.commit_group;\n");

    float o[16][4];
#pragma unroll
    for (int nt = 0; nt < 16; nt++)
#pragma unroll
        for (int r = 0; r < 4; r++) o[nt][r] = 0.f;
    float m0 = -INFINITY, m1 = -INFINITY, l0 = 0.f, l1 = 0.f;

    const int nkv = qt + 1;
    const int arow = (lane & 7) + ((lane >> 3) & 1) * 8;
    const int acol8 = (lane >> 4) * 8;
    const int bro8 = (lane & 7) + ((lane >> 4) << 3);
    const int bco8 = ((lane >> 3) & 1) * 8;
    const int vro8 = (lane & 7) + ((lane >> 3) & 1) * 8;
    const int vco8 = (lane >> 4) * 8;

    for (int kt = 0; kt < nkv; kt++) {
        asm volatile("cp.async.wait_group 0;\n");
        __syncthreads();

        LOADTILE(uV, Vg, kt*AQ);
        asm volatile("cp.async.commit_group;\n");

        // ---- S = (Qh+Ql) K^T ----
        float s[8][4];
#pragma unroll
        for (int t = 0; t < 8; t++)
#pragma unroll
            for (int r = 0; r < 4; r++) s[t][r] = 0.f;

#pragma unroll
        for (int ks = 0; ks < 8; ks++) {
            uint32_t qh4[4], ql4[4];
            uint32_t aoff = ((warp*16 + arow)*APD + ks*16 + acol8)*2;
            ldsm4(qh4, uQh + aoff);
            ldsm4(ql4, uQl + aoff);
#pragma unroll
            for (int bt = 0; bt < 4; bt++) {
                uint32_t kh4[4];
                uint32_t boff = ((bt*16 + bro8)*APD + ks*16 + bco8)*2;
                ldsm4(kh4, uK + boff);
                mma16816(s[2*bt],   qh4, kh4);
                mma16816(s[2*bt],   ql4, kh4);
                mma16816(s[2*bt+1], qh4, kh4+2);
                mma16816(s[2*bt+1], ql4, kh4+2);
            }
        }

        // ---- causal mask on diagonal tile ----
        if (kt == qt) {
            int rl0 = warp*16 + (lane >> 2);
            int cb = (lane & 3) * 2;
#pragma unroll
            for (int t = 0; t < 8; t++) {
                int c0 = t*8 + cb, c1 = c0 + 1;
                if (c0 > rl0)     s[t][0] = -INFINITY;
                if (c1 > rl0)     s[t][1] = -INFINITY;
                if (c0 > rl0 + 8) s[t][2] = -INFINITY;
                if (c1 > rl0 + 8) s[t][3] = -INFINITY;
            }
        }

        // ---- online softmax ----
        float mt0 = -INFINITY, mt1 = -INFINITY;
#pragma unroll
        for (int t = 0; t < 8; t++) {
            mt0 = fmaxf(mt0, fmaxf(s[t][0], s[t][1]));
            mt1 = fmaxf(mt1, fmaxf(s[t][2], s[t][3]));
        }
        mt0 = fmaxf(mt0, __shfl_xor_sync(0xffffffffu, mt0, 1));
        mt0 = fmaxf(mt0, __shfl_xor_sync(0xffffffffu, mt0, 2));
        mt1 = fmaxf(mt1, __shfl_xor_sync(0xffffffffu, mt1, 1));
        mt1 = fmaxf(mt1, __shfl_xor_sync(0xffffffffu, mt1, 2));
        float mn0 = fmaxf(m0, mt0), mn1 = fmaxf(m1, mt1);
        float corr0 = __expf(m0 - mn0), corr1 = __expf(m1 - mn1);
        m0 = mn0; m1 = mn1;

        float p[8][4];
        float sum0 = 0.f, sum1 = 0.f;
#pragma unroll
        for (int t = 0; t < 8; t++) {
            p[t][0] = __expf(s[t][0] - mn0);
            p[t][1] = __expf(s[t][1] - mn0);
            p[t][2] = __expf(s[t][2] - mn1);
            p[t][3] = __expf(s[t][3] - mn1);
            sum0 += p[t][0] + p[t][1];
            sum1 += p[t][2] + p[t][3];
        }
        sum0 += __shfl_xor_sync(0xffffffffu, sum0, 1);
        sum0 += __shfl_xor_sync(0xffffffffu, sum0, 2);
        sum1 += __shfl_xor_sync(0xffffffffu, sum1, 1);
        sum1 += __shfl_xor_sync(0xffffffffu, sum1, 2);
        l0 = l0 * corr0 + sum0;
        l1 = l1 * corr1 + sum1;

        // split P -> hi/lo A-fragments
        uint32_t ph[4][4], pl[4][4];
#pragma unroll
        for (int c = 0; c < 4; c++) {
            split2h(p[2*c][0],   p[2*c][1],   ph[c][0], pl[c][0]);
            split2h(p[2*c][2],   p[2*c][3],   ph[c][1], pl[c][1]);
            split2h(p[2*c+1][0], p[2*c+1][1], ph[c][2], pl[c][2]);
            split2h(p[2*c+1][2], p[2*c+1][3], ph[c][3], pl[c][3]);
        }

#pragma unroll
        for (int nt = 0; nt < 16; nt++) {
            o[nt][0] *= corr0; o[nt][1] *= corr0;
            o[nt][2] *= corr1; o[nt][3] *= corr1;
        }

        asm volatile("cp.async.wait_group 0;\n");   // V ready
        __syncthreads();

        if (kt + 1 < nkv) {
            LOADTILE(uK, Kg, (kt+1)*AQ);
        }
        asm volatile("cp.async.commit_group;\n");

        // ---- O += (Ph+Pl) V ----
#pragma unroll
        for (int c = 0; c < 4; c++) {
#pragma unroll
            for (int np = 0; np < 8; np++) {
                uint32_t vh4[4];
                uint32_t voff = ((c*16 + vro8)*APD + np*16 + vco8)*2;
                ldsm4t(vh4, uV + voff);
                mma16816(o[2*np],   ph[c], vh4);
                mma16816(o[2*np],   pl[c], vh4);
                mma16816(o[2*np+1], ph[c], vh4+2);
                mma16816(o[2*np+1], pl[c], vh4+2);
            }
        }
    }

    // ---- finalize ----
    float inv0 = 1.f / l0, inv1 = 1.f / l1;
    size_t r0g = rowbase + q0 + warp*16 + (lane >> 2);
    size_t cg  = colh + (lane & 3)*2;
#pragma unroll
    for (int nt = 0; nt < 16; nt++) {
        uint32_t hi0, lo0, hi1, lo1;
        split2h(o[nt][0]*inv0, o[nt][1]*inv0, hi0, lo0);
        split2h(o[nt][2]*inv1, o[nt][3]*inv1, hi1, lo1);
        size_t off0 = r0g*DIM + cg + nt*8;
        size_t off1 = (r0g+8)*DIM + cg + nt*8;
        *(uint32_t*)(Ohi + off0) = hi0;
        *(uint32_t*)(Olo + off0) = lo0;
        *(uint32_t*)(Ohi + off1) = hi1;
        *(uint32_t*)(Olo + off1) = lo1;
    }
}

// ============================================================
extern "C" void kernel_launch(void* const* d_in, const int* in_sizes, int n_in,
                              void* d_out, int out_size)
{
    const float* x   = (const float*)d_in[0];
    const float* wq  = (const float*)d_in[1];
    const float* wk  = (const float*)d_in[2];
    const float* wv  = (const float*)d_in[3];
    const float* wo  = (const float*)d_in[4];
    const float* fco = (const float*)d_in[5];
    const float* fsi = (const float*)d_in[6];
    float* out = (float*)d_out;

    __half *Xhi, *Xlo, *W, *Qhi, *Qlo, *Kh, *Vh, *Ohi, *Olo;
    cudaGetSymbolAddress((void**)&Xhi, g_Xhi);
    cudaGetSymbolAddress((void**)&Xlo, g_Xlo);
    cudaGetSymbolAddress((void**)&W,   g_W);
    cudaGetSymbolAddress((void**)&Qhi, g_Qhi);
    cudaGetSymbolAddress((void**)&Qlo, g_Qlo);
    cudaGetSymbolAddress((void**)&Kh,  g_Kh);
    cudaGetSymbolAddress((void**)&Vh,  g_Vh);
    cudaGetSymbolAddress((void**)&Ohi, g_Ohi);
    cudaGetSymbolAddress((void**)&Olo, g_Olo);

    cudaFuncSetAttribute(gemm_fp16x2,
        cudaFuncAttributeMaxDynamicSharedMemorySize, GEMM_SMEM);
    cudaFuncSetAttribute(attn_tc_kernel,
        cudaFuncAttributeMaxDynamicSharedMemorySize, ATTN_SMEM);

    const int nX4 = MROWS * DIM / 4;
    const int nW4 = DIM * DIM / 4;

    split_kernel<<<(nX4 + 255)/256, 256>>>(x, Xhi, Xlo, nX4);
    dim3 cgrid((nW4 + 255)/256, 4);
    cvt4_kernel<<<cgrid, 256>>>(wq, wk, wv, wo, W, nW4);

    // fused QKV projection + rope + split epilogue
    dim3 qkvgrid(DIM/GBN, MROWS/GBM, 3);   // (16, 32, 3)
    gemm_fp16x2<<<qkvgrid, 256, GEMM_SMEM>>>(
        Xhi, Xlo, W,
        Qhi, Qlo, Kh, Vh,
        nullptr, fco, fsi, 1);

    dim3 agrid(SEQ / AQ, NH, BATCH);       // (32, 16, 2)
    attn_tc_kernel<<<agrid, 128, ATTN_SMEM>>>(Qhi, Qlo, Kh, Vh, Ohi, Olo);

    // output projection (mode 3: fp32 store)
    dim3 ogrid(DIM/GBN, MROWS/GBM, 1);
    gemm_fp16x2<<<ogrid, 256, GEMM_SMEM>>>(
        Ohi, Olo, W + 3*WSZ,
        nullptr, nullptr, nullptr, nullptr,
        out, fco, fsi, 0);
}

// round 8
// speedup vs baseline: 6.7677x; 1.0651x over previous
#include <cuda_runtime.h>
#include <cuda_fp16.h>
#include <math.h>
#include <stdint.h>

#define DIM   2048
#define NH    16
#define HD    128
#define SEQ   2048
#define BATCH 2
#define MROWS (BATCH*SEQ)   // 4096
#define WSZ   ((size_t)DIM*DIM)

// ---- scratch (device globals, all fp16) ----
__device__ __half g_Xhi[(size_t)MROWS*DIM];
__device__ __half g_Xlo[(size_t)MROWS*DIM];
__device__ __half g_W[4][WSZ];            // plain fp16, [K,N]
__device__ __half g_Qhi[(size_t)MROWS*DIM];
__device__ __half g_Qlo[(size_t)MROWS*DIM];
__device__ __half g_Kh [(size_t)MROWS*DIM];
__device__ __half g_Vh [(size_t)MROWS*DIM];
__device__ __half g_Ohi[(size_t)MROWS*DIM];
__device__ __half g_Olo[(size_t)MROWS*DIM];

// ---------- PTX helpers ----------
__device__ __forceinline__ void cp16(uint32_t dst, const void* src) {
    asm volatile("cp.async.cg.shared.global [%0], [%1], 16;\n" :: "r"(dst), "l"(src));
}
__device__ __forceinline__ void ldsm4(uint32_t* r, uint32_t a) {
    asm volatile("ldmatrix.sync.aligned.m8n8.x4.shared.b16 {%0,%1,%2,%3}, [%4];\n"
        : "=r"(r[0]), "=r"(r[1]), "=r"(r[2]), "=r"(r[3]) : "r"(a));
}
__device__ __forceinline__ void ldsm4t(uint32_t* r, uint32_t a) {
    asm volatile("ldmatrix.sync.aligned.m8n8.x4.trans.shared.b16 {%0,%1,%2,%3}, [%4];\n"
        : "=r"(r[0]), "=r"(r[1]), "=r"(r[2]), "=r"(r[3]) : "r"(a));
}
__device__ __forceinline__ void mma16816(float* c, const uint32_t* a, const uint32_t* b) {
    asm volatile("mma.sync.aligned.m16n8k16.row.col.f32.f16.f16.f32 "
        "{%0,%1,%2,%3}, {%4,%5,%6,%7}, {%8,%9}, {%0,%1,%2,%3};\n"
        : "+f"(c[0]), "+f"(c[1]), "+f"(c[2]), "+f"(c[3])
        : "r"(a[0]), "r"(a[1]), "r"(a[2]), "r"(a[3]), "r"(b[0]), "r"(b[1]));
}
__device__ __forceinline__ uint32_t packh(float x, float y) {
    __half2 t = __floats2half2_rn(x, y);
    return *(uint32_t*)&t;
}
__device__ __forceinline__ void split2h(float x, float y, uint32_t& hi, uint32_t& lo) {
    float hx = __half2float(__float2half_rn(x));
    float hy = __half2float(__float2half_rn(y));
    hi = packh(hx, hy);
    lo = packh(x - hx, y - hy);
}
__device__ __forceinline__ uint32_t smem_u32(const void* p) {
    return (uint32_t)__cvta_generic_to_shared(p);
}

// ============================================================
// fp32 -> fp16 hi/lo split, 8 elem/thread, uint4 stores
// ============================================================
__global__ __launch_bounds__(256) void split_kernel(
    const float* __restrict__ in, __half* __restrict__ hi,
    __half* __restrict__ lo, int n8)
{
    int i = blockIdx.x * 256 + threadIdx.x;
    if (i >= n8) return;
    float4 a = ((const float4*)in)[2*i];
    float4 b = ((const float4*)in)[2*i+1];
    uint4 h, l;
    split2h(a.x, a.y, h.x, l.x);
    split2h(a.z, a.w, h.y, l.y);
    split2h(b.x, b.y, h.z, l.z);
    split2h(b.z, b.w, h.w, l.w);
    ((uint4*)hi)[i] = h;
    ((uint4*)lo)[i] = l;
}

// fp32 -> fp16 convert, all 4 weights, 8 elem/thread, uint4 stores
__global__ __launch_bounds__(256) void cvt4_kernel(
    const float* __restrict__ w0, const float* __restrict__ w1,
    const float* __restrict__ w2, const float* __restrict__ w3,
    __half* __restrict__ out, int n8)
{
    int i = blockIdx.x * 256 + threadIdx.x;
    if (i >= n8) return;
    int z = blockIdx.y;
    const float* in = (z == 0) ? w0 : (z == 1) ? w1 : (z == 2) ? w2 : w3;
    __half* o = out + (size_t)z * WSZ;
    float4 a = ((const float4*)in)[2*i];
    float4 b = ((const float4*)in)[2*i+1];
    uint4 r;
    r.x = packh(a.x, a.y); r.y = packh(a.z, a.w);
    r.z = packh(b.x, b.y); r.w = packh(b.z, b.w);
    ((uint4*)o)[i] = r;
}

// ============================================================
// Persistent fp16x2 mma.sync GEMM: C = (Ah+Al) @ B, BK=64,
// 2-stage cp.async ring continuous ACROSS tiles, 2 CTAs/SM.
// tile id: z = tile/512, ty = (tile%512)/16, tx = tile%16
// mode per tile (fused): z=0 rope+scale+split Q, z=1 rope K, z=2 V; else fp32 out
// ============================================================
#define GBM 128
#define GBN 128
#define GBK 64
#define APAD 72
#define BPAD 136
#define SAB (GBM*APAD*2)            // 18432
#define SBB (GBK*BPAD*2)            // 17408
#define STAGE (2*SAB + SBB)         // 54272
#define GEMM_SMEM (2*STAGE)         // 108544 -> 2 CTAs/SM
#define CPT 32                       // chunks per tile (DIM/GBK)
#define TPZ (MROWS/GBM * DIM/GBN)    // 512 tiles per z

__global__ __launch_bounds__(256, 2) void gemm_fp16x2(
    const __half* __restrict__ Ah, const __half* __restrict__ Al,
    const __half* __restrict__ B,
    __half* __restrict__ Qh, __half* __restrict__ Ql,
    __half* __restrict__ Kh, __half* __restrict__ Vh,
    float* __restrict__ Cout,
    const float* __restrict__ fcos, const float* __restrict__ fsin,
    int fused, int ntiles)
{
    extern __shared__ char smraw[];
    const uint32_t sb = smem_u32(smraw);

    const int tid  = threadIdx.x;
    const int bid  = blockIdx.x;
    const int G    = gridDim.x;
    const int warp = tid >> 5, lane = tid & 31;
    const int wm = warp >> 2, wn = warp & 3;

    // issue chunk #myc of this CTA's own sequence (tile bid + (myc/32)*G, chunk myc%32)
    auto issue_chunk = [&](int myc) {
        int t = bid + (myc >> 5) * G;
        if (t >= ntiles) return;
        int z   = t / TPZ;
        int rem = t - z * TPZ;
        int row0 = (rem >> 4) * GBM;
        int col0 = (rem & 15) * GBN;
        const __half* bp = B + (size_t)z * WSZ;
        const uint32_t base = sb + (uint32_t)(myc & 1) * STAGE;
        const int k0 = (myc & (CPT-1)) * GBK;
        for (int idx = tid; idx < 1024; idx += 256) {
            int r = idx >> 3, o = (idx & 7) * 8;
            uint32_t d = base + (uint32_t)(r * APAD + o) * 2;
            size_t g = (size_t)(row0 + r) * DIM + k0 + o;
            cp16(d,       Ah + g);
            cp16(d + SAB, Al + g);
        }
        for (int idx = tid; idx < 1024; idx += 256) {
            int r = idx >> 4, o = (idx & 15) * 8;
            uint32_t d = base + 2*SAB + (uint32_t)(r * BPAD + o) * 2;
            cp16(d, bp + (size_t)(k0 + r) * DIM + col0 + o);
        }
    };

    issue_chunk(0);
    asm volatile("cp.async.commit_group;\n");
    issue_chunk(1);
    asm volatile("cp.async.commit_group;\n");

    const int arow  = (lane & 7) + ((lane >> 3) & 1) * 8;
    const int acol8 = (lane >> 4) * 8;
    const int brow8 = (lane & 7) + ((lane >> 3) & 1) * 8;
    const int bnc8  = (lane >> 4) * 8;
    const float qscale = 0.08838834764831845f;

    int myc = 0;
    for (int t = bid; t < ntiles; t += G) {
        const int z   = t / TPZ;
        const int rem = t - z * TPZ;
        const int row0 = (rem >> 4) * GBM;
        const int col0 = (rem & 15) * GBN;
        const int mode = fused ? z : 3;

        float acc[4][4][4];
#pragma unroll
        for (int i = 0; i < 4; i++)
#pragma unroll
            for (int j = 0; j < 4; j++)
#pragma unroll
                for (int r = 0; r < 4; r++) acc[i][j][r] = 0.f;

        for (int i = 0; i < CPT; i++, myc++) {
            asm volatile("cp.async.wait_group 1;\n");
            __syncthreads();

            const uint32_t base = sb + (uint32_t)(myc & 1) * STAGE;
            const uint32_t bAh = base, bAl = base + SAB;
            const uint32_t bB  = base + 2*SAB;

#pragma unroll
            for (int ks = 0; ks < 4; ks++) {
                const int acol = ks * 16 + acol8;
                uint32_t bfr[4][2];
                const int brow = ks * 16 + brow8;
#pragma unroll
                for (int hh = 0; hh < 2; hh++) {
                    int nc = wn * 32 + hh * 16 + bnc8;
                    uint32_t t4[4];
                    ldsm4t(t4, bB + (uint32_t)(brow * BPAD + nc) * 2);
                    bfr[hh*2][0] = t4[0]; bfr[hh*2][1] = t4[1];
                    bfr[hh*2+1][0] = t4[2]; bfr[hh*2+1][1] = t4[3];
                }
                uint32_t af[4][4];
#pragma unroll
                for (int mt = 0; mt < 4; mt++)
                    ldsm4(af[mt], bAh + (uint32_t)((wm*64 + mt*16 + arow) * APAD + acol) * 2);
#pragma unroll
                for (int mt = 0; mt < 4; mt++)
#pragma unroll
                    for (int nt = 0; nt < 4; nt++)
                        mma16816(acc[mt][nt], af[mt], bfr[nt]);
#pragma unroll
                for (int mt = 0; mt < 4; mt++)
                    ldsm4(af[mt], bAl + (uint32_t)((wm*64 + mt*16 + arow) * APAD + acol) * 2);
#pragma unroll
                for (int mt = 0; mt < 4; mt++)
#pragma unroll
                    for (int nt = 0; nt < 4; nt++)
                        mma16816(acc[mt][nt], af[mt], bfr[nt]);
            }

            __syncthreads();              // buffer myc&1 free for reuse
            issue_chunk(myc + 2);         // lands in buffer (myc)&1
            asm volatile("cp.async.commit_group;\n");
        }

        // ---- epilogue (registers+global only; overlaps in-flight cp.async) ----
#pragma unroll
        for (int mt = 0; mt < 4; mt++) {
#pragma unroll
            for (int nt = 0; nt < 4; nt++) {
                int r = row0 + wm * 64 + mt * 16 + (lane >> 2);
                int c = col0 + wn * 32 + nt * 8 + (lane & 3) * 2;
                float a0 = acc[mt][nt][0], a1 = acc[mt][nt][1];
                float a2 = acc[mt][nt][2], a3 = acc[mt][nt][3];
                size_t o0 = (size_t)r * DIM + c, o1 = (size_t)(r + 8) * DIM + c;
                if (mode == 3) {
                    *(float2*)(Cout + o0) = make_float2(a0, a1);
                    *(float2*)(Cout + o1) = make_float2(a2, a3);
                } else if (mode == 2) {
                    *(uint32_t*)(Vh + o0) = packh(a0, a1);
                    *(uint32_t*)(Vh + o1) = packh(a2, a3);
                } else {
                    int i2 = (c & (HD - 1)) >> 1;
                    int s0 = r & (SEQ - 1), s1 = (r + 8) & (SEQ - 1);
                    float c0 = fcos[s0 * (HD/2) + i2], n0 = fsin[s0 * (HD/2) + i2];
                    float c1 = fcos[s1 * (HD/2) + i2], n1 = fsin[s1 * (HD/2) + i2];
                    float t0 = a0 * c0 - a1 * n0, t1 = a0 * n0 + a1 * c0;
                    float t2 = a2 * c1 - a3 * n1, t3 = a2 * n1 + a3 * c1;
                    if (mode == 0) {
                        t0 *= qscale; t1 *= qscale; t2 *= qscale; t3 *= qscale;
                        uint32_t h0, l0, h1, l1;
                        split2h(t0, t1, h0, l0);
                        split2h(t2, t3, h1, l1);
                        *(uint32_t*)(Qh + o0) = h0; *(uint32_t*)(Ql + o0) = l0;
                        *(uint32_t*)(Qh + o1) = h1; *(uint32_t*)(Ql + o1) = l1;
                    } else {
                        *(uint32_t*)(Kh + o0) = packh(t0, t1);
                        *(uint32_t*)(Kh + o1) = packh(t2, t3);
                    }
                }
            }
        }
    }
}

// ============================================================
// fp16x2 causal flash attention, 64x64 tiles, mma.sync.
// Q split hi/lo; K, V plain fp16. P split in registers.
// ============================================================
#define AQ  64
#define APD 136
#define TILE_E (AQ*APD)
#define ATTN_SMEM (4*TILE_E*2)     // Qh,Ql,K,V = 69632 -> 3 CTAs/SM

__global__ __launch_bounds__(128) void attn_tc_kernel(
    const __half* __restrict__ Qhi, const __half* __restrict__ Qlo,
    const __half* __restrict__ Kg,  const __half* __restrict__ Vg,
    __half* __restrict__ Ohi, __half* __restrict__ Olo)
{
    extern __shared__ __half sm[];
    __half* sQh = sm;
    __half* sQl = sQh + TILE_E;
    __half* sK  = sQl + TILE_E;
    __half* sV  = sK  + TILE_E;
    const uint32_t uQh = smem_u32(sQh);
    const uint32_t uQl = smem_u32(sQl);
    const uint32_t uK  = smem_u32(sK);
    const uint32_t uV  = smem_u32(sV);

    const int tid = threadIdx.x, warp = tid >> 5, lane = tid & 31;
    const int qt = (int)(gridDim.x - 1 - blockIdx.x);   // heavy tiles first
    const int h = blockIdx.y, b = blockIdx.z;
    const int q0 = qt * AQ;
    const size_t rowbase = (size_t)b * SEQ;
    const size_t colh = (size_t)h * HD;

#define LOADTILE(dstu, src, r0) do {                                           \
    for (int c0_ = tid; c0_ < 1024; c0_ += 128) {                              \
        int r_ = c0_ >> 4, o_ = (c0_ & 15) * 8;                                \
        cp16((dstu) + (r_*APD + o_)*2,                                         \
             (src) + (rowbase + (r0) + r_)*DIM + colh + o_);                   \
    } } while (0)

    LOADTILE(uQh, Qhi, q0);
    LOADTILE(uQl, Qlo, q0);
    LOADTILE(uK,  Kg,  0);
    asm volatile("cp.async.commit_group;\n");

    float o[16][4];
#pragma unroll
    for (int nt = 0; nt < 16; nt++)
#pragma unroll
        for (int r = 0; r < 4; r++) o[nt][r] = 0.f;
    float m0 = -INFINITY, m1 = -INFINITY, l0 = 0.f, l1 = 0.f;

    const int nkv = qt + 1;
    const int arow = (lane & 7) + ((lane >> 3) & 1) * 8;
    const int acol8 = (lane >> 4) * 8;
    const int bro8 = (lane & 7) + ((lane >> 4) << 3);
    const int bco8 = ((lane >> 3) & 1) * 8;
    const int vro8 = (lane & 7) + ((lane >> 3) & 1) * 8;
    const int vco8 = (lane >> 4) * 8;

    for (int kt = 0; kt < nkv; kt++) {
        asm volatile("cp.async.wait_group 0;\n");
        __syncthreads();

        LOADTILE(uV, Vg, kt*AQ);
        asm volatile("cp.async.commit_group;\n");

        // ---- S = (Qh+Ql) K^T ----
        float s[8][4];
#pragma unroll
        for (int t = 0; t < 8; t++)
#pragma unroll
            for (int r = 0; r < 4; r++) s[t][r] = 0.f;

#pragma unroll
        for (int ks = 0; ks < 8; ks++) {
            uint32_t qh4[4], ql4[4];
            uint32_t aoff = ((warp*16 + arow)*APD + ks*16 + acol8)*2;
            ldsm4(qh4, uQh + aoff);
            ldsm4(ql4, uQl + aoff);
#pragma unroll
            for (int bt = 0; bt < 4; bt++) {
                uint32_t kh4[4];
                uint32_t boff = ((bt*16 + bro8)*APD + ks*16 + bco8)*2;
                ldsm4(kh4, uK + boff);
                mma16816(s[2*bt],   qh4, kh4);
                mma16816(s[2*bt],   ql4, kh4);
                mma16816(s[2*bt+1], qh4, kh4+2);
                mma16816(s[2*bt+1], ql4, kh4+2);
            }
        }

        if (kt == qt) {
            int rl0 = warp*16 + (lane >> 2);
            int cb = (lane & 3) * 2;
#pragma unroll
            for (int t = 0; t < 8; t++) {
                int c0 = t*8 + cb, c1 = c0 + 1;
                if (c0 > rl0)     s[t][0] = -INFINITY;
                if (c1 > rl0)     s[t][1] = -INFINITY;
                if (c0 > rl0 + 8) s[t][2] = -INFINITY;
                if (c1 > rl0 + 8) s[t][3] = -INFINITY;
            }
        }

        float mt0 = -INFINITY, mt1 = -INFINITY;
#pragma unroll
        for (int t = 0; t < 8; t++) {
            mt0 = fmaxf(mt0, fmaxf(s[t][0], s[t][1]));
            mt1 = fmaxf(mt1, fmaxf(s[t][2], s[t][3]));
        }
        mt0 = fmaxf(mt0, __shfl_xor_sync(0xffffffffu, mt0, 1));
        mt0 = fmaxf(mt0, __shfl_xor_sync(0xffffffffu, mt0, 2));
        mt1 = fmaxf(mt1, __shfl_xor_sync(0xffffffffu, mt1, 1));
        mt1 = fmaxf(mt1, __shfl_xor_sync(0xffffffffu, mt1, 2));
        float mn0 = fmaxf(m0, mt0), mn1 = fmaxf(m1, mt1);
        float corr0 = __expf(m0 - mn0), corr1 = __expf(m1 - mn1);
        m0 = mn0; m1 = mn1;

        float p[8][4];
        float sum0 = 0.f, sum1 = 0.f;
#pragma unroll
        for (int t = 0; t < 8; t++) {
            p[t][0] = __expf(s[t][0] - mn0);
            p[t][1] = __expf(s[t][1] - mn0);
            p[t][2] = __expf(s[t][2] - mn1);
            p[t][3] = __expf(s[t][3] - mn1);
            sum0 += p[t][0] + p[t][1];
            sum1 += p[t][2] + p[t][3];
        }
        sum0 += __shfl_xor_sync(0xffffffffu, sum0, 1);
        sum0 += __shfl_xor_sync(0xffffffffu, sum0, 2);
        sum1 += __shfl_xor_sync(0xffffffffu, sum1, 1);
        sum1 += __shfl_xor_sync(0xffffffffu, sum1, 2);
        l0 = l0 * corr0 + sum0;
        l1 = l1 * corr1 + sum1;

        uint32_t ph[4][4], pl[4][4];
#pragma unroll
        for (int c = 0; c < 4; c++) {
            split2h(p[2*c][0],   p[2*c][1],   ph[c][0], pl[c][0]);
            split2h(p[2*c][2],   p[2*c][3],   ph[c][1], pl[c][1]);
            split2h(p[2*c+1][0], p[2*c+1][1], ph[c][2], pl[c][2]);
            split2h(p[2*c+1][2], p[2*c+1][3], ph[c][3], pl[c][3]);
        }

#pragma unroll
        for (int nt = 0; nt < 16; nt++) {
            o[nt][0] *= corr0; o[nt][1] *= corr0;
            o[nt][2] *= corr1; o[nt][3] *= corr1;
        }

        asm volatile("cp.async.wait_group 0;\n");
        __syncthreads();

        if (kt + 1 < nkv) {
            LOADTILE(uK, Kg, (kt+1)*AQ);
        }
        asm volatile("cp.async.commit_group;\n");

#pragma unroll
        for (int c = 0; c < 4; c++) {
#pragma unroll
            for (int np = 0; np < 8; np++) {
                uint32_t vh4[4];
                uint32_t voff = ((c*16 + vro8)*APD + np*16 + vco8)*2;
                ldsm4t(vh4, uV + voff);
                mma16816(o[2*np],   ph[c], vh4);
                mma16816(o[2*np],   pl[c], vh4);
                mma16816(o[2*np+1], ph[c], vh4+2);
                mma16816(o[2*np+1], pl[c], vh4+2);
            }
        }
    }

    float inv0 = 1.f / l0, inv1 = 1.f / l1;
    size_t r0g = rowbase + q0 + warp*16 + (lane >> 2);
    size_t cg  = colh + (lane & 3)*2;
#pragma unroll
    for (int nt = 0; nt < 16; nt++) {
        uint32_t hi0, lo0, hi1, lo1;
        split2h(o[nt][0]*inv0, o[nt][1]*inv0, hi0, lo0);
        split2h(o[nt][2]*inv1, o[nt][3]*inv1, hi1, lo1);
        size_t off0 = r0g*DIM + cg + nt*8;
        size_t off1 = (r0g+8)*DIM + cg + nt*8;
        *(uint32_t*)(Ohi + off0) = hi0;
        *(uint32_t*)(Olo + off0) = lo0;
        *(uint32_t*)(Ohi + off1) = hi1;
        *(uint32_t*)(Olo + off1) = lo1;
    }
}

// ============================================================
extern "C" void kernel_launch(void* const* d_in, const int* in_sizes, int n_in,
                              void* d_out, int out_size)
{
    const float* x   = (const float*)d_in[0];
    const float* wq  = (const float*)d_in[1];
    const float* wk  = (const float*)d_in[2];
    const float* wv  = (const float*)d_in[3];
    const float* wo  = (const float*)d_in[4];
    const float* fco = (const float*)d_in[5];
    const float* fsi = (const float*)d_in[6];
    float* out = (float*)d_out;

    __half *Xhi, *Xlo, *W, *Qhi, *Qlo, *Kh, *Vh, *Ohi, *Olo;
    cudaGetSymbolAddress((void**)&Xhi, g_Xhi);
    cudaGetSymbolAddress((void**)&Xlo, g_Xlo);
    cudaGetSymbolAddress((void**)&W,   g_W);
    cudaGetSymbolAddress((void**)&Qhi, g_Qhi);
    cudaGetSymbolAddress((void**)&Qlo, g_Qlo);
    cudaGetSymbolAddress((void**)&Kh,  g_Kh);
    cudaGetSymbolAddress((void**)&Vh,  g_Vh);
    cudaGetSymbolAddress((void**)&Ohi, g_Ohi);
    cudaGetSymbolAddress((void**)&Olo, g_Olo);

    cudaFuncSetAttribute(gemm_fp16x2,
        cudaFuncAttributeMaxDynamicSharedMemorySize, GEMM_SMEM);
    cudaFuncSetAttribute(attn_tc_kernel,
        cudaFuncAttributeMaxDynamicSharedMemorySize, ATTN_SMEM);

    const int nX8 = MROWS * DIM / 8;
    const int nW8 = DIM * DIM / 8;

    split_kernel<<<(nX8 + 255)/256, 256>>>(x, Xhi, Xlo, nX8);
    dim3 cgrid((nW8 + 255)/256, 4);
    cvt4_kernel<<<cgrid, 256>>>(wq, wk, wv, wo, W, nW8);

    // persistent fused QKV projection: 1536 tiles over 296 CTAs
    gemm_fp16x2<<<296, 256, GEMM_SMEM>>>(
        Xhi, Xlo, W,
        Qhi, Qlo, Kh, Vh,
        nullptr, fco, fsi, 1, 3*TPZ);

    dim3 agrid(SEQ / AQ, NH, BATCH);       // (32, 16, 2)
    attn_tc_kernel<<<agrid, 128, ATTN_SMEM>>>(Qhi, Qlo, Kh, Vh, Ohi, Olo);

    // persistent output projection: 512 tiles over 296 CTAs
    gemm_fp16x2<<<296, 256, GEMM_SMEM>>>(
        Ohi, Olo, W + 3*WSZ,
        nullptr, nullptr, nullptr, nullptr,
        out, fco, fsi, 0, TPZ);
}